// round 5
// baseline (speedup 1.0000x reference)
#include <cuda_runtime.h>
#include <cuda_bf16.h>
#include <cstdint>

#define D 128
#define NNODES 50000
#define NEDGES 600000
#define THREADS 256
#define SCAN_BLOCKS ((NNODES + 255) / 256)   // 196

// ---------------------------------------------------------------------------
// Device-global scratch (allocation-free rule)
// ---------------------------------------------------------------------------
__device__ float g_h[(size_t)NNODES * D];     // layer-1 output
__device__ int   g_deg[NNODES];
__device__ int   g_off[NNODES + 1];
__device__ int   g_cursor[NNODES];
__device__ int   g_adj[NEDGES];
__device__ int   g_bsum[256];                 // block sums for 3-phase scan
// split weights, K-major [n][k], 4 matrices: W1a, W1b, W2a, W2b
__device__ __nv_bfloat16 g_whi[4 * D * D];
__device__ __nv_bfloat16 g_wlo[4 * D * D];

// ---------------------------------------------------------------------------
// helpers
// ---------------------------------------------------------------------------
__device__ __forceinline__ uint32_t smem_u32(const void* p) {
    uint32_t a;
    asm("{ .reg .u64 t; cvta.to.shared.u64 t, %1; cvt.u32.u64 %0, t; }" : "=r"(a) : "l"(p));
    return a;
}

__device__ __forceinline__ void ldsm_x4(uint32_t& r0, uint32_t& r1, uint32_t& r2, uint32_t& r3,
                                        uint32_t addr) {
    asm volatile("ldmatrix.sync.aligned.m8n8.x4.shared.b16 {%0,%1,%2,%3}, [%4];"
                 : "=r"(r0), "=r"(r1), "=r"(r2), "=r"(r3) : "r"(addr));
}

__device__ __forceinline__ void mma_bf16(float& c0, float& c1, float& c2, float& c3,
                                         uint32_t a0, uint32_t a1, uint32_t a2, uint32_t a3,
                                         uint32_t b0, uint32_t b1) {
    asm volatile("mma.sync.aligned.m16n8k16.row.col.f32.bf16.bf16.f32 "
                 "{%0,%1,%2,%3}, {%4,%5,%6,%7}, {%8,%9}, {%0,%1,%2,%3};"
                 : "+f"(c0), "+f"(c1), "+f"(c2), "+f"(c3)
                 : "r"(a0), "r"(a1), "r"(a2), "r"(a3), "r"(b0), "r"(b1));
}

__device__ __forceinline__ void split2(float v0, float v1, uint32_t& hi2, uint32_t& lo2) {
    __nv_bfloat16 h0 = __float2bfloat16(v0), h1 = __float2bfloat16(v1);
    __nv_bfloat16 l0 = __float2bfloat16(v0 - __bfloat162float(h0));
    __nv_bfloat16 l1 = __float2bfloat16(v1 - __bfloat162float(h1));
    __nv_bfloat162 hp; hp.x = h0; hp.y = h1;
    __nv_bfloat162 lp; lp.x = l0; lp.y = l1;
    hi2 = *(uint32_t*)&hp;
    lo2 = *(uint32_t*)&lp;
}

// ---------------------------------------------------------------------------
// 1: histogram
// ---------------------------------------------------------------------------
__global__ void k_hist(const int* __restrict__ dst) {
    int e = blockIdx.x * blockDim.x + threadIdx.x;
    if (e < NEDGES) atomicAdd(&g_deg[dst[e]], 1);
}

// ---------------------------------------------------------------------------
// 2: scan phase A (per-256-chunk exclusive scan) + fused weight split
//    grid = 256 blocks x 256 threads. Blocks 0..195 also do scan chunks.
// ---------------------------------------------------------------------------
__global__ __launch_bounds__(256)
void k_scanA_wsplit(const float* __restrict__ W0, const float* __restrict__ W1,
                    const float* __restrict__ W2, const float* __restrict__ W3) {
    __shared__ int wsum[8];
    const int b = blockIdx.x, tid = threadIdx.x, lane = tid & 31, wd = tid >> 5;

    if (b < SCAN_BLOCKS) {
        int i = b * 256 + tid;
        int v = (i < NNODES) ? g_deg[i] : 0;
        if (i < NNODES) g_deg[i] = 0;            // re-zero for next call
        int s = v;
        #pragma unroll
        for (int o = 1; o < 32; o <<= 1) {
            int t = __shfl_up_sync(0xFFFFFFFFu, s, o);
            if (lane >= o) s += t;
        }
        if (lane == 31) wsum[wd] = s;
        __syncthreads();
        if (wd == 0) {
            int x = (lane < 8) ? wsum[lane] : 0;
            #pragma unroll
            for (int o = 1; o < 8; o <<= 1) {
                int t = __shfl_up_sync(0xFFFFFFFFu, x, o);
                if (lane >= o) x += t;
            }
            if (lane < 8) wsum[lane] = x;        // inclusive warp sums
        }
        __syncthreads();
        int excl = (wd ? wsum[wd - 1] : 0) + s - v;
        if (i < NNODES) g_off[i] = excl;         // partial (pre block offset)
        if (tid == 255) g_bsum[b] = wsum[7];
    }

    // fused weight transpose+split: gidx over 4*128*128 = 65536 = grid exactly
    {
        int gidx = b * 256 + tid;
        int mat = gidx >> 14;
        int idx = gidx & 16383;
        const float* W = (mat == 0) ? W0 : (mat == 1) ? W1 : (mat == 2) ? W2 : W3;
        int n = idx >> 7, k = idx & 127;
        float w = W[k * D + n];
        __nv_bfloat16 h = __float2bfloat16(w);
        g_whi[gidx] = h;
        g_wlo[gidx] = __float2bfloat16(w - __bfloat162float(h));
    }
}

// ---------------------------------------------------------------------------
// 3: scan phase B (single block scans the 196 block sums, exclusive)
// ---------------------------------------------------------------------------
__global__ __launch_bounds__(256)
void k_scanB() {
    __shared__ int wsum[8];
    const int tid = threadIdx.x, lane = tid & 31, wd = tid >> 5;
    int v = (tid < SCAN_BLOCKS) ? g_bsum[tid] : 0;
    int s = v;
    #pragma unroll
    for (int o = 1; o < 32; o <<= 1) {
        int t = __shfl_up_sync(0xFFFFFFFFu, s, o);
        if (lane >= o) s += t;
    }
    if (lane == 31) wsum[wd] = s;
    __syncthreads();
    if (wd == 0) {
        int x = (lane < 8) ? wsum[lane] : 0;
        #pragma unroll
        for (int o = 1; o < 8; o <<= 1) {
            int t = __shfl_up_sync(0xFFFFFFFFu, x, o);
            if (lane >= o) x += t;
        }
        if (lane < 8) wsum[lane] = x;
    }
    __syncthreads();
    int excl = (wd ? wsum[wd - 1] : 0) + s - v;
    if (tid < SCAN_BLOCKS) g_bsum[tid] = excl;
}

// ---------------------------------------------------------------------------
// 4: scan phase C (add block offsets, produce final offsets + cursors)
// ---------------------------------------------------------------------------
__global__ void k_scanC() {
    int i = blockIdx.x * blockDim.x + threadIdx.x;
    if (i < NNODES) {
        int off = g_off[i] + g_bsum[i >> 8];
        g_off[i] = off;
        g_cursor[i] = off;
    }
    if (i == 0) g_off[NNODES] = NEDGES;
}

// ---------------------------------------------------------------------------
// 5: fill CSR adjacency
// ---------------------------------------------------------------------------
__global__ void k_fill(const int* __restrict__ src, const int* __restrict__ dst) {
    int e = blockIdx.x * blockDim.x + threadIdx.x;
    if (e < NEDGES) {
        int pos = atomicAdd(&g_cursor[dst[e]], 1);
        g_adj[pos] = src[e];
    }
}

// ---------------------------------------------------------------------------
// 6/7: fused GIN layer: gather + bf16x3-split + HMMA MLP
//   out = maybe_relu( relu( (h + sum_nbr h) @ Wa + ba ) @ Wb + bb )
// Per CTA: 128 node rows. 8 warps, 4(m)x2(n) warp grid, tile 32x64.
// smem rows padded to 272B -> conflict-free ldmatrix.
// ---------------------------------------------------------------------------
#define PB 272
#define SMEM_BA   0
#define SMEM_BB   512
#define SMEM_AHI  1024
#define ABUF_SZ   (128 * PB)
#define SMEM_ALO  (SMEM_AHI + ABUF_SZ)
#define SMEM_W    (SMEM_ALO + ABUF_SZ)
#define SMEM_TOTAL (SMEM_W + 4 * ABUF_SZ)     // 209920 B

__global__ __launch_bounds__(THREADS, 1)
void k_gin_fused(const float* __restrict__ x,
                 const __nv_bfloat16* __restrict__ wa_hi, const __nv_bfloat16* __restrict__ wa_lo,
                 const __nv_bfloat16* __restrict__ wb_hi, const __nv_bfloat16* __restrict__ wb_lo,
                 const float* __restrict__ ba, const float* __restrict__ bb,
                 float* __restrict__ out, int relu_out) {
    extern __shared__ char smem[];
    const uint32_t sb = smem_u32(smem);
    const int tid = threadIdx.x, wid = tid >> 5, lane = tid & 31;
    const int row0 = blockIdx.x * 128;

    // ---- biases ----
    if (tid < 128) {
        ((float*)(smem + SMEM_BA))[tid] = ba[tid];
        ((float*)(smem + SMEM_BB))[tid] = bb[tid];
    }

    // ---- weights -> padded smem ----
    {
        const __nv_bfloat16* Wp[4] = {wa_hi, wa_lo, wb_hi, wb_lo};
        #pragma unroll 4
        for (int i = tid; i < 4 * 128 * 16; i += THREADS) {
            int mat = i >> 11;
            int rem = i & 2047;
            int row = rem >> 4;
            int ch  = rem & 15;
            uint4 v = ((const uint4*)Wp[mat])[(row << 4) + ch];
            *(uint4*)(smem + SMEM_W + mat * ABUF_SZ + row * PB + ch * 16) = v;
        }
    }

    // ---- fused gather + split: A = split(h[r] + sum_nbr h), warp-per-row ----
    {
        const float4* hp = (const float4*)x;
        char* hi = smem + SMEM_AHI;
        char* lo = smem + SMEM_ALO;
        #pragma unroll 1
        for (int rr = 0; rr < 16; rr++) {
            const int r = wid * 16 + rr;
            const int grow = row0 + r;
            float4 acc = make_float4(0.f, 0.f, 0.f, 0.f);
            if (grow < NNODES) {
                acc = hp[(size_t)grow * 32 + lane];
                int beg = g_off[grow], end = g_off[grow + 1];
                int p = beg;
                for (; p + 8 <= end; p += 8) {
                    float4 v[8];
                    #pragma unroll
                    for (int q = 0; q < 8; q++) {
                        int s = g_adj[p + q];
                        v[q] = hp[(size_t)s * 32 + lane];
                    }
                    #pragma unroll
                    for (int q = 0; q < 8; q++) {
                        acc.x += v[q].x; acc.y += v[q].y;
                        acc.z += v[q].z; acc.w += v[q].w;
                    }
                }
                for (; p < end; ++p) {
                    int s = g_adj[p];
                    float4 v = hp[(size_t)s * 32 + lane];
                    acc.x += v.x; acc.y += v.y; acc.z += v.z; acc.w += v.w;
                }
            }
            uint32_t h2a, l2a, h2b, l2b;
            split2(acc.x, acc.y, h2a, l2a);
            split2(acc.z, acc.w, h2b, l2b);
            char* hrow = hi + r * PB + lane * 8;
            char* lrow = lo + r * PB + lane * 8;
            *(uint32_t*)(hrow)     = h2a;
            *(uint32_t*)(hrow + 4) = h2b;
            *(uint32_t*)(lrow)     = l2a;
            *(uint32_t*)(lrow + 4) = l2b;
        }
    }
    __syncthreads();

    // warp tiling
    const int warp_m = wid & 3;
    const int warp_n = wid >> 2;
    const int m0 = warp_m * 32;
    const int n0 = warp_n * 64;

    const uint32_t a_off = (uint32_t)((m0 + (lane & 15)) * PB + (lane >> 4) * 16);
    const uint32_t b_off = (uint32_t)((n0 + ((lane >> 4) << 3) + (lane & 7)) * PB
                                      + ((lane >> 3) & 1) * 16);

    const uint32_t Ahi = sb + SMEM_AHI;
    const uint32_t Alo = sb + SMEM_ALO;

    float acc[2][8][4];

    auto run_gemm = [&](uint32_t Bhi, uint32_t Blo) {
        #pragma unroll
        for (int tm = 0; tm < 2; tm++)
            #pragma unroll
            for (int tn = 0; tn < 8; tn++)
                #pragma unroll
                for (int q = 0; q < 4; q++) acc[tm][tn][q] = 0.f;

        #pragma unroll
        for (int s = 0; s < 8; s++) {
            const uint32_t kb = s * 32;
            uint32_t ah[2][4], al[2][4];
            ldsm_x4(ah[0][0], ah[0][1], ah[0][2], ah[0][3], Ahi + a_off + kb);
            ldsm_x4(ah[1][0], ah[1][1], ah[1][2], ah[1][3], Ahi + a_off + 16 * PB + kb);
            ldsm_x4(al[0][0], al[0][1], al[0][2], al[0][3], Alo + a_off + kb);
            ldsm_x4(al[1][0], al[1][1], al[1][2], al[1][3], Alo + a_off + 16 * PB + kb);

            uint32_t bh[4][4], bl[4][4];
            #pragma unroll
            for (int p = 0; p < 4; p++) {
                ldsm_x4(bh[p][0], bh[p][1], bh[p][2], bh[p][3], Bhi + b_off + p * 16 * PB + kb);
                ldsm_x4(bl[p][0], bl[p][1], bl[p][2], bl[p][3], Blo + b_off + p * 16 * PB + kb);
            }

            #pragma unroll
            for (int tm = 0; tm < 2; tm++) {
                #pragma unroll
                for (int p = 0; p < 4; p++) {
                    #pragma unroll
                    for (int half = 0; half < 2; half++) {
                        const int tn = p * 2 + half;
                        float* c = acc[tm][tn];
                        mma_bf16(c[0], c[1], c[2], c[3],
                                 ah[tm][0], ah[tm][1], ah[tm][2], ah[tm][3],
                                 bh[p][half * 2], bh[p][half * 2 + 1]);
                        mma_bf16(c[0], c[1], c[2], c[3],
                                 al[tm][0], al[tm][1], al[tm][2], al[tm][3],
                                 bh[p][half * 2], bh[p][half * 2 + 1]);
                        mma_bf16(c[0], c[1], c[2], c[3],
                                 ah[tm][0], ah[tm][1], ah[tm][2], ah[tm][3],
                                 bl[p][half * 2], bl[p][half * 2 + 1]);
                    }
                }
            }
        }
    };

    // ---- GEMM1 ----
    run_gemm(sb + SMEM_W + 0 * ABUF_SZ, sb + SMEM_W + 1 * ABUF_SZ);
    __syncthreads();

    // ---- epilogue 1: H = split(relu(acc + ba)) -> A buffers ----
    {
        const float* bav = (const float*)(smem + SMEM_BA);
        #pragma unroll
        for (int tm = 0; tm < 2; tm++) {
            #pragma unroll
            for (int tn = 0; tn < 8; tn++) {
                const int col = n0 + tn * 8 + (lane & 3) * 2;
                const float b0v = bav[col], b1v = bav[col + 1];
                const int r_lo = m0 + tm * 16 + (lane >> 2);
                float v0 = fmaxf(acc[tm][tn][0] + b0v, 0.f);
                float v1 = fmaxf(acc[tm][tn][1] + b1v, 0.f);
                float v2 = fmaxf(acc[tm][tn][2] + b0v, 0.f);
                float v3 = fmaxf(acc[tm][tn][3] + b1v, 0.f);
                uint32_t h2, l2;
                split2(v0, v1, h2, l2);
                *(uint32_t*)(smem + SMEM_AHI + r_lo * PB + col * 2) = h2;
                *(uint32_t*)(smem + SMEM_ALO + r_lo * PB + col * 2) = l2;
                split2(v2, v3, h2, l2);
                *(uint32_t*)(smem + SMEM_AHI + (r_lo + 8) * PB + col * 2) = h2;
                *(uint32_t*)(smem + SMEM_ALO + (r_lo + 8) * PB + col * 2) = l2;
            }
        }
    }
    __syncthreads();

    // ---- GEMM2 ----
    run_gemm(sb + SMEM_W + 2 * ABUF_SZ, sb + SMEM_W + 3 * ABUF_SZ);

    // ---- epilogue 2: out = maybe_relu(acc + bb) ----
    {
        const float* bbv = (const float*)(smem + SMEM_BB);
        #pragma unroll
        for (int tm = 0; tm < 2; tm++) {
            #pragma unroll
            for (int tn = 0; tn < 8; tn++) {
                const int col = n0 + tn * 8 + (lane & 3) * 2;
                const float b0v = bbv[col], b1v = bbv[col + 1];
                const int r_lo = row0 + m0 + tm * 16 + (lane >> 2);
                float v0 = acc[tm][tn][0] + b0v;
                float v1 = acc[tm][tn][1] + b1v;
                float v2 = acc[tm][tn][2] + b0v;
                float v3 = acc[tm][tn][3] + b1v;
                if (relu_out) {
                    v0 = fmaxf(v0, 0.f); v1 = fmaxf(v1, 0.f);
                    v2 = fmaxf(v2, 0.f); v3 = fmaxf(v3, 0.f);
                }
                if (r_lo < NNODES)
                    *(float2*)(out + (size_t)r_lo * D + col) = make_float2(v0, v1);
                if (r_lo + 8 < NNODES)
                    *(float2*)(out + (size_t)(r_lo + 8) * D + col) = make_float2(v2, v3);
            }
        }
    }
}

// ---------------------------------------------------------------------------
// launch
// ---------------------------------------------------------------------------
extern "C" void kernel_launch(void* const* d_in, const int* in_sizes, int n_in,
                              void* d_out, int out_size) {
    const float* inputs = (const float*)d_in[0];
    const int*   src    = (const int*)  d_in[1];
    const int*   dst    = (const int*)  d_in[2];
    const float* W1a    = (const float*)d_in[3];
    const float* b1a    = (const float*)d_in[4];
    const float* W1b    = (const float*)d_in[5];
    const float* b1b    = (const float*)d_in[6];
    const float* W2a    = (const float*)d_in[7];
    const float* b2a    = (const float*)d_in[8];
    const float* W2b    = (const float*)d_in[9];
    const float* b2b    = (const float*)d_in[10];
    float* out = (float*)d_out;

    float* gh = nullptr;
    __nv_bfloat16 *gwhi = nullptr, *gwlo = nullptr;
    cudaGetSymbolAddress((void**)&gh, g_h);
    cudaGetSymbolAddress((void**)&gwhi, g_whi);
    cudaGetSymbolAddress((void**)&gwlo, g_wlo);

    cudaFuncSetAttribute(k_gin_fused, cudaFuncAttributeMaxDynamicSharedMemorySize, SMEM_TOTAL);

    const int edge_blocks = (NEDGES + THREADS - 1) / THREADS;
    const int mlp_blocks  = (NNODES + 127) / 128;

    k_hist<<<edge_blocks, THREADS>>>(dst);                        // 1
    k_scanA_wsplit<<<256, 256>>>(W1a, W1b, W2a, W2b);             // 2
    k_scanB<<<1, 256>>>();                                        // 3
    k_scanC<<<SCAN_BLOCKS, 256>>>();                              // 4
    k_fill<<<edge_blocks, THREADS>>>(src, dst);                   // 5

    // layer 1
    k_gin_fused<<<mlp_blocks, THREADS, SMEM_TOTAL>>>(             // 6
        inputs, gwhi + 0 * D * D, gwlo + 0 * D * D,
                gwhi + 1 * D * D, gwlo + 1 * D * D,
        b1a, b1b, gh, 1);

    // layer 2
    k_gin_fused<<<mlp_blocks, THREADS, SMEM_TOTAL>>>(             // 7
        gh, gwhi + 2 * D * D, gwlo + 2 * D * D,
            gwhi + 3 * D * D, gwlo + 3 * D * D,
        b2a, b2b, out, 0);
}

// round 6
// speedup vs baseline: 1.3793x; 1.3793x over previous
#include <cuda_runtime.h>
#include <cuda_bf16.h>
#include <cstdint>

#define D 128
#define NNODES 50000
#define NEDGES 600000
#define THREADS 256
#define SCAN_BLOCKS ((NNODES + 255) / 256)   // 196

// ---------------------------------------------------------------------------
// Device-global scratch (allocation-free rule)
// ---------------------------------------------------------------------------
__device__ float g_x[(size_t)NNODES * D];     // gathered features
__device__ float g_h[(size_t)NNODES * D];     // layer-1 output
__device__ int   g_deg[NNODES];
__device__ int   g_off[NNODES + 1];
__device__ int   g_cursor[NNODES];
__device__ int   g_adj[NEDGES];
__device__ int   g_bsum[256];
// split weights, K-major [n][k], 4 matrices: W1a, W1b, W2a, W2b
__device__ __nv_bfloat16 g_whi[4 * D * D];
__device__ __nv_bfloat16 g_wlo[4 * D * D];

// ---------------------------------------------------------------------------
// helpers
// ---------------------------------------------------------------------------
__device__ __forceinline__ uint32_t smem_u32(const void* p) {
    uint32_t a;
    asm("{ .reg .u64 t; cvta.to.shared.u64 t, %1; cvt.u32.u64 %0, t; }" : "=r"(a) : "l"(p));
    return a;
}

__device__ __forceinline__ void ldsm_x4(uint32_t& r0, uint32_t& r1, uint32_t& r2, uint32_t& r3,
                                        uint32_t addr) {
    asm volatile("ldmatrix.sync.aligned.m8n8.x4.shared.b16 {%0,%1,%2,%3}, [%4];"
                 : "=r"(r0), "=r"(r1), "=r"(r2), "=r"(r3) : "r"(addr));
}

__device__ __forceinline__ void mma_bf16(float& c0, float& c1, float& c2, float& c3,
                                         uint32_t a0, uint32_t a1, uint32_t a2, uint32_t a3,
                                         uint32_t b0, uint32_t b1) {
    asm volatile("mma.sync.aligned.m16n8k16.row.col.f32.bf16.bf16.f32 "
                 "{%0,%1,%2,%3}, {%4,%5,%6,%7}, {%8,%9}, {%0,%1,%2,%3};"
                 : "+f"(c0), "+f"(c1), "+f"(c2), "+f"(c3)
                 : "r"(a0), "r"(a1), "r"(a2), "r"(a3), "r"(b0), "r"(b1));
}

__device__ __forceinline__ void split2(float v0, float v1, uint32_t& hi2, uint32_t& lo2) {
    __nv_bfloat16 h0 = __float2bfloat16(v0), h1 = __float2bfloat16(v1);
    __nv_bfloat16 l0 = __float2bfloat16(v0 - __bfloat162float(h0));
    __nv_bfloat16 l1 = __float2bfloat16(v1 - __bfloat162float(h1));
    __nv_bfloat162 hp; hp.x = h0; hp.y = h1;
    __nv_bfloat162 lp; lp.x = l0; lp.y = l1;
    hi2 = *(uint32_t*)&hp;
    lo2 = *(uint32_t*)&lp;
}

// ---------------------------------------------------------------------------
// 0: histogram
// ---------------------------------------------------------------------------
__global__ void k_hist(const int* __restrict__ dst) {
    int e = blockIdx.x * blockDim.x + threadIdx.x;
    if (e < NEDGES) atomicAdd(&g_deg[dst[e]], 1);
}

// ---------------------------------------------------------------------------
// 1: scan phase A (per-256-chunk exclusive scan) + fused weight split
// ---------------------------------------------------------------------------
__global__ __launch_bounds__(256)
void k_scanA_wsplit(const float* __restrict__ W0, const float* __restrict__ W1,
                    const float* __restrict__ W2, const float* __restrict__ W3) {
    __shared__ int wsum[8];
    const int b = blockIdx.x, tid = threadIdx.x, lane = tid & 31, wd = tid >> 5;

    if (b < SCAN_BLOCKS) {
        int i = b * 256 + tid;
        int v = (i < NNODES) ? g_deg[i] : 0;
        if (i < NNODES) g_deg[i] = 0;            // re-zero for next call
        int s = v;
        #pragma unroll
        for (int o = 1; o < 32; o <<= 1) {
            int t = __shfl_up_sync(0xFFFFFFFFu, s, o);
            if (lane >= o) s += t;
        }
        if (lane == 31) wsum[wd] = s;
        __syncthreads();
        if (wd == 0) {
            int x = (lane < 8) ? wsum[lane] : 0;
            #pragma unroll
            for (int o = 1; o < 8; o <<= 1) {
                int t = __shfl_up_sync(0xFFFFFFFFu, x, o);
                if (lane >= o) x += t;
            }
            if (lane < 8) wsum[lane] = x;
        }
        __syncthreads();
        int excl = (wd ? wsum[wd - 1] : 0) + s - v;
        if (i < NNODES) g_off[i] = excl;         // partial (pre block offset)
        if (tid == 255) g_bsum[b] = wsum[7];
    }

    // fused weight transpose+split: gidx over 4*128*128 = 65536 = grid exactly
    {
        int gidx = b * 256 + tid;
        int mat = gidx >> 14;
        int idx = gidx & 16383;
        const float* W = (mat == 0) ? W0 : (mat == 1) ? W1 : (mat == 2) ? W2 : W3;
        int n = idx >> 7, k = idx & 127;
        float w = W[k * D + n];
        __nv_bfloat16 h = __float2bfloat16(w);
        g_whi[gidx] = h;
        g_wlo[gidx] = __float2bfloat16(w - __bfloat162float(h));
    }
}

// ---------------------------------------------------------------------------
// 2: scan phase BC: each block redundantly reduces block-sums[0..b-1],
//    then finalizes its 256 offsets + cursors
// ---------------------------------------------------------------------------
__global__ __launch_bounds__(256)
void k_scanBC() {
    __shared__ int pre_s;
    __shared__ int wred[8];
    const int b = blockIdx.x, tid = threadIdx.x, lane = tid & 31, wd = tid >> 5;

    int s = 0;
    for (int j = tid; j < b; j += 256) s += g_bsum[j];
    #pragma unroll
    for (int o = 16; o > 0; o >>= 1) s += __shfl_down_sync(0xFFFFFFFFu, s, o);
    if (lane == 0) wred[wd] = s;
    __syncthreads();
    if (tid == 0) {
        int t = 0;
        #pragma unroll
        for (int w = 0; w < 8; w++) t += wred[w];
        pre_s = t;
    }
    __syncthreads();

    int i = b * 256 + tid;
    if (i < NNODES) {
        int off = g_off[i] + pre_s;
        g_off[i] = off;
        g_cursor[i] = off;
    }
    if (b == 0 && tid == 0) g_off[NNODES] = NEDGES;
}

// ---------------------------------------------------------------------------
// 3: fill CSR adjacency   <- ncu-profiled slot (launch index 3)
// ---------------------------------------------------------------------------
__global__ void k_fill(const int* __restrict__ src, const int* __restrict__ dst) {
    int e = blockIdx.x * blockDim.x + threadIdx.x;
    if (e < NEDGES) {
        int pos = atomicAdd(&g_cursor[dst[e]], 1);
        g_adj[pos] = src[e];
    }
}

// ---------------------------------------------------------------------------
// gather: x[i] = h[i] + sum_{s in adj(i)} h[s]   (one warp per node)
// ---------------------------------------------------------------------------
__global__ __launch_bounds__(THREADS)
void k_gather(const float* __restrict__ h, float* __restrict__ x) {
    int warp = (blockIdx.x * blockDim.x + threadIdx.x) >> 5;
    int lane = threadIdx.x & 31;
    if (warp >= NNODES) return;
    const float4* hp = (const float4*)h;
    int beg = g_off[warp], end = g_off[warp + 1];
    float4 acc = hp[(size_t)warp * 32 + lane];
    int p = beg;
    for (; p + 4 <= end; p += 4) {
        int s0 = g_adj[p], s1 = g_adj[p + 1], s2 = g_adj[p + 2], s3 = g_adj[p + 3];
        float4 v0 = hp[(size_t)s0 * 32 + lane];
        float4 v1 = hp[(size_t)s1 * 32 + lane];
        float4 v2 = hp[(size_t)s2 * 32 + lane];
        float4 v3 = hp[(size_t)s3 * 32 + lane];
        acc.x += v0.x + v1.x + v2.x + v3.x;
        acc.y += v0.y + v1.y + v2.y + v3.y;
        acc.z += v0.z + v1.z + v2.z + v3.z;
        acc.w += v0.w + v1.w + v2.w + v3.w;
    }
    for (; p < end; ++p) {
        int s = g_adj[p];
        float4 v = hp[(size_t)s * 32 + lane];
        acc.x += v.x; acc.y += v.y; acc.z += v.z; acc.w += v.w;
    }
    ((float4*)x)[(size_t)warp * 32 + lane] = acc;
}

// ---------------------------------------------------------------------------
// HMMA fused MLP: out = maybe_relu( relu(x@Wa+ba) @ Wb + bb )
// bf16x3 split, fp32 accum, mma.sync.m16n8k16. 8 warps, 4(m)x2(n), tile 32x64.
// ---------------------------------------------------------------------------
#define PB 272
#define SMEM_BA   0
#define SMEM_BB   512
#define SMEM_AHI  1024
#define ABUF_SZ   (128 * PB)
#define SMEM_ALO  (SMEM_AHI + ABUF_SZ)
#define SMEM_W    (SMEM_ALO + ABUF_SZ)
#define SMEM_TOTAL (SMEM_W + 4 * ABUF_SZ)     // 209920 B

__global__ __launch_bounds__(THREADS, 1)
void k_mlp_hmma(const float* __restrict__ x,
                const __nv_bfloat16* __restrict__ wa_hi, const __nv_bfloat16* __restrict__ wa_lo,
                const __nv_bfloat16* __restrict__ wb_hi, const __nv_bfloat16* __restrict__ wb_lo,
                const float* __restrict__ ba, const float* __restrict__ bb,
                float* __restrict__ out, int relu_out) {
    extern __shared__ char smem[];
    const uint32_t sb = smem_u32(smem);
    const int tid = threadIdx.x, wid = tid >> 5, lane = tid & 31;
    const int row0 = blockIdx.x * 128;

    // ---- biases ----
    if (tid < 128) {
        ((float*)(smem + SMEM_BA))[tid] = ba[tid];
        ((float*)(smem + SMEM_BB))[tid] = bb[tid];
    }

    // ---- weights -> padded smem (16B chunks) ----
    {
        const __nv_bfloat16* Wp[4] = {wa_hi, wa_lo, wb_hi, wb_lo};
        #pragma unroll 4
        for (int i = tid; i < 4 * 128 * 16; i += THREADS) {
            int mat = i >> 11;
            int rem = i & 2047;
            int row = rem >> 4;
            int ch  = rem & 15;
            uint4 v = ((const uint4*)Wp[mat])[(row << 4) + ch];
            *(uint4*)(smem + SMEM_W + mat * ABUF_SZ + row * PB + ch * 16) = v;
        }
    }

    // ---- A tile: load fp32, split to bf16 hi/lo ----
    {
        int r  = tid >> 1;
        int c0 = (tid & 1) * 64;
        int grow = row0 + r;
        char* hi = smem + SMEM_AHI + r * PB + c0 * 2;
        char* lo = smem + SMEM_ALO + r * PB + c0 * 2;
        if (grow < NNODES) {
            const float4* xp = (const float4*)(x + (size_t)grow * D + c0);
            #pragma unroll
            for (int c = 0; c < 64; c += 4) {
                float4 v = xp[c >> 2];
                uint32_t h2a, l2a, h2b, l2b;
                split2(v.x, v.y, h2a, l2a);
                split2(v.z, v.w, h2b, l2b);
                *(uint32_t*)(hi + c * 2)     = h2a;
                *(uint32_t*)(hi + c * 2 + 4) = h2b;
                *(uint32_t*)(lo + c * 2)     = l2a;
                *(uint32_t*)(lo + c * 2 + 4) = l2b;
            }
        } else {
            #pragma unroll
            for (int c = 0; c < 64; c += 4) {
                *(uint32_t*)(hi + c * 2)     = 0u;
                *(uint32_t*)(hi + c * 2 + 4) = 0u;
                *(uint32_t*)(lo + c * 2)     = 0u;
                *(uint32_t*)(lo + c * 2 + 4) = 0u;
            }
        }
    }
    __syncthreads();

    const int warp_m = wid & 3;
    const int warp_n = wid >> 2;
    const int m0 = warp_m * 32;
    const int n0 = warp_n * 64;

    const uint32_t a_off = (uint32_t)((m0 + (lane & 15)) * PB + (lane >> 4) * 16);
    const uint32_t b_off = (uint32_t)((n0 + ((lane >> 4) << 3) + (lane & 7)) * PB
                                      + ((lane >> 3) & 1) * 16);

    const uint32_t Ahi = sb + SMEM_AHI;
    const uint32_t Alo = sb + SMEM_ALO;

    float acc[2][8][4];

    auto run_gemm = [&](uint32_t Bhi, uint32_t Blo) {
        #pragma unroll
        for (int tm = 0; tm < 2; tm++)
            #pragma unroll
            for (int tn = 0; tn < 8; tn++)
                #pragma unroll
                for (int q = 0; q < 4; q++) acc[tm][tn][q] = 0.f;

        #pragma unroll
        for (int s = 0; s < 8; s++) {
            const uint32_t kb = s * 32;
            uint32_t ah[2][4], al[2][4];
            ldsm_x4(ah[0][0], ah[0][1], ah[0][2], ah[0][3], Ahi + a_off + kb);
            ldsm_x4(ah[1][0], ah[1][1], ah[1][2], ah[1][3], Ahi + a_off + 16 * PB + kb);
            ldsm_x4(al[0][0], al[0][1], al[0][2], al[0][3], Alo + a_off + kb);
            ldsm_x4(al[1][0], al[1][1], al[1][2], al[1][3], Alo + a_off + 16 * PB + kb);

            uint32_t bh[4][4], bl[4][4];
            #pragma unroll
            for (int p = 0; p < 4; p++) {
                ldsm_x4(bh[p][0], bh[p][1], bh[p][2], bh[p][3], Bhi + b_off + p * 16 * PB + kb);
                ldsm_x4(bl[p][0], bl[p][1], bl[p][2], bl[p][3], Blo + b_off + p * 16 * PB + kb);
            }

            #pragma unroll
            for (int tm = 0; tm < 2; tm++) {
                #pragma unroll
                for (int p = 0; p < 4; p++) {
                    #pragma unroll
                    for (int half = 0; half < 2; half++) {
                        const int tn = p * 2 + half;
                        float* c = acc[tm][tn];
                        mma_bf16(c[0], c[1], c[2], c[3],
                                 ah[tm][0], ah[tm][1], ah[tm][2], ah[tm][3],
                                 bh[p][half * 2], bh[p][half * 2 + 1]);
                        mma_bf16(c[0], c[1], c[2], c[3],
                                 al[tm][0], al[tm][1], al[tm][2], al[tm][3],
                                 bh[p][half * 2], bh[p][half * 2 + 1]);
                        mma_bf16(c[0], c[1], c[2], c[3],
                                 ah[tm][0], ah[tm][1], ah[tm][2], ah[tm][3],
                                 bl[p][half * 2], bl[p][half * 2 + 1]);
                    }
                }
            }
        }
    };

    // ---- GEMM1 ----
    run_gemm(sb + SMEM_W + 0 * ABUF_SZ, sb + SMEM_W + 1 * ABUF_SZ);
    __syncthreads();

    // ---- epilogue 1: H = split(relu(acc + ba)) -> A buffers ----
    {
        const float* bav = (const float*)(smem + SMEM_BA);
        #pragma unroll
        for (int tm = 0; tm < 2; tm++) {
            #pragma unroll
            for (int tn = 0; tn < 8; tn++) {
                const int col = n0 + tn * 8 + (lane & 3) * 2;
                const float b0v = bav[col], b1v = bav[col + 1];
                const int r_lo = m0 + tm * 16 + (lane >> 2);
                float v0 = fmaxf(acc[tm][tn][0] + b0v, 0.f);
                float v1 = fmaxf(acc[tm][tn][1] + b1v, 0.f);
                float v2 = fmaxf(acc[tm][tn][2] + b0v, 0.f);
                float v3 = fmaxf(acc[tm][tn][3] + b1v, 0.f);
                uint32_t h2, l2;
                split2(v0, v1, h2, l2);
                *(uint32_t*)(smem + SMEM_AHI + r_lo * PB + col * 2) = h2;
                *(uint32_t*)(smem + SMEM_ALO + r_lo * PB + col * 2) = l2;
                split2(v2, v3, h2, l2);
                *(uint32_t*)(smem + SMEM_AHI + (r_lo + 8) * PB + col * 2) = h2;
                *(uint32_t*)(smem + SMEM_ALO + (r_lo + 8) * PB + col * 2) = l2;
            }
        }
    }
    __syncthreads();

    // ---- GEMM2 ----
    run_gemm(sb + SMEM_W + 2 * ABUF_SZ, sb + SMEM_W + 3 * ABUF_SZ);

    // ---- epilogue 2: out = maybe_relu(acc + bb) ----
    {
        const float* bbv = (const float*)(smem + SMEM_BB);
        #pragma unroll
        for (int tm = 0; tm < 2; tm++) {
            #pragma unroll
            for (int tn = 0; tn < 8; tn++) {
                const int col = n0 + tn * 8 + (lane & 3) * 2;
                const float b0v = bbv[col], b1v = bbv[col + 1];
                const int r_lo = row0 + m0 + tm * 16 + (lane >> 2);
                float v0 = acc[tm][tn][0] + b0v;
                float v1 = acc[tm][tn][1] + b1v;
                float v2 = acc[tm][tn][2] + b0v;
                float v3 = acc[tm][tn][3] + b1v;
                if (relu_out) {
                    v0 = fmaxf(v0, 0.f); v1 = fmaxf(v1, 0.f);
                    v2 = fmaxf(v2, 0.f); v3 = fmaxf(v3, 0.f);
                }
                if (r_lo < NNODES)
                    *(float2*)(out + (size_t)r_lo * D + col) = make_float2(v0, v1);
                if (r_lo + 8 < NNODES)
                    *(float2*)(out + (size_t)(r_lo + 8) * D + col) = make_float2(v2, v3);
            }
        }
    }
}

// ---------------------------------------------------------------------------
// launch
// ---------------------------------------------------------------------------
extern "C" void kernel_launch(void* const* d_in, const int* in_sizes, int n_in,
                              void* d_out, int out_size) {
    const float* inputs = (const float*)d_in[0];
    const int*   src    = (const int*)  d_in[1];
    const int*   dst    = (const int*)  d_in[2];
    const float* W1a    = (const float*)d_in[3];
    const float* b1a    = (const float*)d_in[4];
    const float* W1b    = (const float*)d_in[5];
    const float* b1b    = (const float*)d_in[6];
    const float* W2a    = (const float*)d_in[7];
    const float* b2a    = (const float*)d_in[8];
    const float* W2b    = (const float*)d_in[9];
    const float* b2b    = (const float*)d_in[10];
    float* out = (float*)d_out;

    float *gx = nullptr, *gh = nullptr;
    __nv_bfloat16 *gwhi = nullptr, *gwlo = nullptr;
    cudaGetSymbolAddress((void**)&gx, g_x);
    cudaGetSymbolAddress((void**)&gh, g_h);
    cudaGetSymbolAddress((void**)&gwhi, g_whi);
    cudaGetSymbolAddress((void**)&gwlo, g_wlo);

    cudaFuncSetAttribute(k_mlp_hmma, cudaFuncAttributeMaxDynamicSharedMemorySize, SMEM_TOTAL);

    const int edge_blocks = (NEDGES + THREADS - 1) / THREADS;
    const int gath_blocks = (NNODES * 32 + THREADS - 1) / THREADS;
    const int mlp_blocks  = (NNODES + 127) / 128;

    k_hist<<<edge_blocks, THREADS>>>(dst);                        // 0
    k_scanA_wsplit<<<256, 256>>>(W1a, W1b, W2a, W2b);             // 1
    k_scanBC<<<SCAN_BLOCKS, 256>>>();                             // 2
    k_fill<<<edge_blocks, THREADS>>>(src, dst);                   // 3  <- profiled

    // layer 1
    k_gather<<<gath_blocks, THREADS>>>(inputs, gx);               // 4
    k_mlp_hmma<<<mlp_blocks, THREADS, SMEM_TOTAL>>>(              // 5
        gx, gwhi + 0 * D * D, gwlo + 0 * D * D,
            gwhi + 1 * D * D, gwlo + 1 * D * D,
        b1a, b1b, gh, 1);

    // layer 2
    k_gather<<<gath_blocks, THREADS>>>(gh, gx);                   // 6
    k_mlp_hmma<<<mlp_blocks, THREADS, SMEM_TOTAL>>>(              // 7
        gx, gwhi + 2 * D * D, gwlo + 2 * D * D,
            gwhi + 3 * D * D, gwlo + 3 * D * D,
        b2a, b2b, out, 0);
}

// round 7
// speedup vs baseline: 1.7244x; 1.2503x over previous
#include <cuda_runtime.h>
#include <cuda_fp16.h>
#include <cstdint>

#define D 128
#define NNODES 50000
#define NEDGES 600000
#define THREADS 256
#define SCAN_BLOCKS ((NNODES + 255) / 256)   // 196

// ---------------------------------------------------------------------------
// Device-global scratch (allocation-free rule)
// ---------------------------------------------------------------------------
__device__ float g_x[(size_t)NNODES * D];     // gathered features
__device__ float g_h[(size_t)NNODES * D];     // layer-1 output
__device__ int   g_deg[NNODES];
__device__ int   g_off[NNODES + 1];
__device__ int   g_cursor[NNODES];
__device__ int   g_adj[NEDGES];
__device__ int   g_bsum[256];
// fp16 weights, K-major [n][k], 4 matrices: W1a, W1b, W2a, W2b
__device__ __half g_w[4 * D * D];

// ---------------------------------------------------------------------------
// helpers
// ---------------------------------------------------------------------------
__device__ __forceinline__ uint32_t smem_u32(const void* p) {
    uint32_t a;
    asm("{ .reg .u64 t; cvta.to.shared.u64 t, %1; cvt.u32.u64 %0, t; }" : "=r"(a) : "l"(p));
    return a;
}

__device__ __forceinline__ void ldsm_x4(uint32_t& r0, uint32_t& r1, uint32_t& r2, uint32_t& r3,
                                        uint32_t addr) {
    asm volatile("ldmatrix.sync.aligned.m8n8.x4.shared.b16 {%0,%1,%2,%3}, [%4];"
                 : "=r"(r0), "=r"(r1), "=r"(r2), "=r"(r3) : "r"(addr));
}

__device__ __forceinline__ void mma_f16(float& c0, float& c1, float& c2, float& c3,
                                        uint32_t a0, uint32_t a1, uint32_t a2, uint32_t a3,
                                        uint32_t b0, uint32_t b1) {
    asm volatile("mma.sync.aligned.m16n8k16.row.col.f32.f16.f16.f32 "
                 "{%0,%1,%2,%3}, {%4,%5,%6,%7}, {%8,%9}, {%0,%1,%2,%3};"
                 : "+f"(c0), "+f"(c1), "+f"(c2), "+f"(c3)
                 : "r"(a0), "r"(a1), "r"(a2), "r"(a3), "r"(b0), "r"(b1));
}

// fp16 two-term split: v = hi + lo, hi = rn(v), lo = rn(v - hi)
__device__ __forceinline__ void split2h(float v0, float v1, uint32_t& hi2, uint32_t& lo2) {
    __half h0 = __float2half_rn(v0), h1 = __float2half_rn(v1);
    __half l0 = __float2half_rn(v0 - __half2float(h0));
    __half l1 = __float2half_rn(v1 - __half2float(h1));
    __half2 hp; hp.x = h0; hp.y = h1;
    __half2 lp; lp.x = l0; lp.y = l1;
    hi2 = *(uint32_t*)&hp;
    lo2 = *(uint32_t*)&lp;
}

// ---------------------------------------------------------------------------
// 0: histogram
// ---------------------------------------------------------------------------
__global__ void k_hist(const int* __restrict__ dst) {
    int e = blockIdx.x * blockDim.x + threadIdx.x;
    if (e < NEDGES) atomicAdd(&g_deg[dst[e]], 1);
}

// ---------------------------------------------------------------------------
// 1: scan phase A (per-256-chunk exclusive scan) + fused weight convert
// ---------------------------------------------------------------------------
__global__ __launch_bounds__(256)
void k_scanA_wsplit(const float* __restrict__ W0, const float* __restrict__ W1,
                    const float* __restrict__ W2, const float* __restrict__ W3) {
    __shared__ int wsum[8];
    const int b = blockIdx.x, tid = threadIdx.x, lane = tid & 31, wd = tid >> 5;

    if (b < SCAN_BLOCKS) {
        int i = b * 256 + tid;
        int v = (i < NNODES) ? g_deg[i] : 0;
        if (i < NNODES) g_deg[i] = 0;            // re-zero for next call
        int s = v;
        #pragma unroll
        for (int o = 1; o < 32; o <<= 1) {
            int t = __shfl_up_sync(0xFFFFFFFFu, s, o);
            if (lane >= o) s += t;
        }
        if (lane == 31) wsum[wd] = s;
        __syncthreads();
        if (wd == 0) {
            int x = (lane < 8) ? wsum[lane] : 0;
            #pragma unroll
            for (int o = 1; o < 8; o <<= 1) {
                int t = __shfl_up_sync(0xFFFFFFFFu, x, o);
                if (lane >= o) x += t;
            }
            if (lane < 8) wsum[lane] = x;
        }
        __syncthreads();
        int excl = (wd ? wsum[wd - 1] : 0) + s - v;
        if (i < NNODES) g_off[i] = excl;
        if (tid == 255) g_bsum[b] = wsum[7];
    }

    // fused weight transpose + fp16 convert: 4*128*128 = 65536 = grid exactly
    {
        int gidx = b * 256 + tid;
        int mat = gidx >> 14;
        int idx = gidx & 16383;
        const float* W = (mat == 0) ? W0 : (mat == 1) ? W1 : (mat == 2) ? W2 : W3;
        int n = idx >> 7, k = idx & 127;
        g_w[gidx] = __float2half_rn(W[k * D + n]);
    }
}

// ---------------------------------------------------------------------------
// 2: scan phase BC
// ---------------------------------------------------------------------------
__global__ __launch_bounds__(256)
void k_scanBC() {
    __shared__ int pre_s;
    __shared__ int wred[8];
    const int b = blockIdx.x, tid = threadIdx.x, lane = tid & 31, wd = tid >> 5;

    int s = 0;
    for (int j = tid; j < b; j += 256) s += g_bsum[j];
    #pragma unroll
    for (int o = 16; o > 0; o >>= 1) s += __shfl_down_sync(0xFFFFFFFFu, s, o);
    if (lane == 0) wred[wd] = s;
    __syncthreads();
    if (tid == 0) {
        int t = 0;
        #pragma unroll
        for (int w = 0; w < 8; w++) t += wred[w];
        pre_s = t;
    }
    __syncthreads();

    int i = b * 256 + tid;
    if (i < NNODES) {
        int off = g_off[i] + pre_s;
        g_off[i] = off;
        g_cursor[i] = off;
    }
    if (b == 0 && tid == 0) g_off[NNODES] = NEDGES;
}

// ---------------------------------------------------------------------------
// 3: fill CSR adjacency
// ---------------------------------------------------------------------------
__global__ void k_fill(const int* __restrict__ src, const int* __restrict__ dst) {
    int e = blockIdx.x * blockDim.x + threadIdx.x;
    if (e < NEDGES) {
        int pos = atomicAdd(&g_cursor[dst[e]], 1);
        g_adj[pos] = src[e];
    }
}

// ---------------------------------------------------------------------------
// gather: x[i] = h[i] + sum_{s in adj(i)} h[s]   (one warp per node)
// ---------------------------------------------------------------------------
__global__ __launch_bounds__(THREADS)
void k_gather(const float* __restrict__ h, float* __restrict__ x) {
    int warp = (blockIdx.x * blockDim.x + threadIdx.x) >> 5;
    int lane = threadIdx.x & 31;
    if (warp >= NNODES) return;
    const float4* hp = (const float4*)h;
    int beg = g_off[warp], end = g_off[warp + 1];
    float4 acc = hp[(size_t)warp * 32 + lane];
    int p = beg;
    for (; p + 4 <= end; p += 4) {
        int s0 = g_adj[p], s1 = g_adj[p + 1], s2 = g_adj[p + 2], s3 = g_adj[p + 3];
        float4 v0 = hp[(size_t)s0 * 32 + lane];
        float4 v1 = hp[(size_t)s1 * 32 + lane];
        float4 v2 = hp[(size_t)s2 * 32 + lane];
        float4 v3 = hp[(size_t)s3 * 32 + lane];
        acc.x += v0.x + v1.x + v2.x + v3.x;
        acc.y += v0.y + v1.y + v2.y + v3.y;
        acc.z += v0.z + v1.z + v2.z + v3.z;
        acc.w += v0.w + v1.w + v2.w + v3.w;
    }
    for (; p < end; ++p) {
        int s = g_adj[p];
        float4 v = hp[(size_t)s * 32 + lane];
        acc.x += v.x; acc.y += v.y; acc.z += v.z; acc.w += v.w;
    }
    ((float4*)x)[(size_t)warp * 32 + lane] = acc;
}

// ---------------------------------------------------------------------------
// HMMA fused MLP (fp16 2-term): out = maybe_relu( relu(x@Wa+ba) @ Wb + bb )
// A = A_hi + A_lo (fp16 pair), W single fp16. 2 MMAs per tile position.
// 8 warps, 4(m)x2(n) warp grid, warp tile 32x64.
// ---------------------------------------------------------------------------
#define PB 272
#define SMEM_BA   0
#define SMEM_BB   512
#define SMEM_AHI  1024
#define ABUF_SZ   (128 * PB)                  // 34816
#define SMEM_ALO  (SMEM_AHI + ABUF_SZ)
#define SMEM_W    (SMEM_ALO + ABUF_SZ)        // 2 x ABUF_SZ: Wa, Wb (fp16)
#define SMEM_TOTAL (SMEM_W + 2 * ABUF_SZ)     // 140288 B

__global__ __launch_bounds__(THREADS, 1)
void k_mlp_hmma(const float* __restrict__ x,
                const __half* __restrict__ wa, const __half* __restrict__ wb,
                const float* __restrict__ ba, const float* __restrict__ bb,
                float* __restrict__ out, int relu_out) {
    extern __shared__ char smem[];
    const uint32_t sb = smem_u32(smem);
    const int tid = threadIdx.x, wid = tid >> 5, lane = tid & 31;
    const int row0 = blockIdx.x * 128;

    // ---- biases ----
    if (tid < 128) {
        ((float*)(smem + SMEM_BA))[tid] = ba[tid];
        ((float*)(smem + SMEM_BB))[tid] = bb[tid];
    }

    // ---- weights -> padded smem (16B chunks); 2 matrices x 2048 chunks ----
    {
        const __half* Wp[2] = {wa, wb};
        #pragma unroll 4
        for (int i = tid; i < 2 * 128 * 16; i += THREADS) {
            int mat = i >> 11;
            int rem = i & 2047;
            int row = rem >> 4;
            int ch  = rem & 15;
            uint4 v = ((const uint4*)Wp[mat])[(row << 4) + ch];
            *(uint4*)(smem + SMEM_W + mat * ABUF_SZ + row * PB + ch * 16) = v;
        }
    }

    // ---- A tile: load fp32, split to fp16 hi/lo ----
    {
        int r  = tid >> 1;
        int c0 = (tid & 1) * 64;
        int grow = row0 + r;
        char* hi = smem + SMEM_AHI + r * PB + c0 * 2;
        char* lo = smem + SMEM_ALO + r * PB + c0 * 2;
        if (grow < NNODES) {
            const float4* xp = (const float4*)(x + (size_t)grow * D + c0);
            #pragma unroll
            for (int c = 0; c < 64; c += 4) {
                float4 v = xp[c >> 2];
                uint32_t h2a, l2a, h2b, l2b;
                split2h(v.x, v.y, h2a, l2a);
                split2h(v.z, v.w, h2b, l2b);
                *(uint32_t*)(hi + c * 2)     = h2a;
                *(uint32_t*)(hi + c * 2 + 4) = h2b;
                *(uint32_t*)(lo + c * 2)     = l2a;
                *(uint32_t*)(lo + c * 2 + 4) = l2b;
            }
        } else {
            #pragma unroll
            for (int c = 0; c < 64; c += 4) {
                *(uint32_t*)(hi + c * 2)     = 0u;
                *(uint32_t*)(hi + c * 2 + 4) = 0u;
                *(uint32_t*)(lo + c * 2)     = 0u;
                *(uint32_t*)(lo + c * 2 + 4) = 0u;
            }
        }
    }
    __syncthreads();

    const int warp_m = wid & 3;
    const int warp_n = wid >> 2;
    const int m0 = warp_m * 32;
    const int n0 = warp_n * 64;

    const uint32_t a_off = (uint32_t)((m0 + (lane & 15)) * PB + (lane >> 4) * 16);
    const uint32_t b_off = (uint32_t)((n0 + ((lane >> 4) << 3) + (lane & 7)) * PB
                                      + ((lane >> 3) & 1) * 16);

    const uint32_t Ahi = sb + SMEM_AHI;
    const uint32_t Alo = sb + SMEM_ALO;

    float acc[2][8][4];

    auto run_gemm = [&](uint32_t Bw) {
        #pragma unroll
        for (int tm = 0; tm < 2; tm++)
            #pragma unroll
            for (int tn = 0; tn < 8; tn++)
                #pragma unroll
                for (int q = 0; q < 4; q++) acc[tm][tn][q] = 0.f;

        #pragma unroll
        for (int s = 0; s < 8; s++) {
            const uint32_t kb = s * 32;
            uint32_t ah[2][4], al[2][4];
            ldsm_x4(ah[0][0], ah[0][1], ah[0][2], ah[0][3], Ahi + a_off + kb);
            ldsm_x4(ah[1][0], ah[1][1], ah[1][2], ah[1][3], Ahi + a_off + 16 * PB + kb);
            ldsm_x4(al[0][0], al[0][1], al[0][2], al[0][3], Alo + a_off + kb);
            ldsm_x4(al[1][0], al[1][1], al[1][2], al[1][3], Alo + a_off + 16 * PB + kb);

            uint32_t bw[4][4];
            #pragma unroll
            for (int p = 0; p < 4; p++)
                ldsm_x4(bw[p][0], bw[p][1], bw[p][2], bw[p][3], Bw + b_off + p * 16 * PB + kb);

            #pragma unroll
            for (int tm = 0; tm < 2; tm++) {
                #pragma unroll
                for (int p = 0; p < 4; p++) {
                    #pragma unroll
                    for (int half = 0; half < 2; half++) {
                        const int tn = p * 2 + half;
                        float* c = acc[tm][tn];
                        mma_f16(c[0], c[1], c[2], c[3],
                                ah[tm][0], ah[tm][1], ah[tm][2], ah[tm][3],
                                bw[p][half * 2], bw[p][half * 2 + 1]);
                        mma_f16(c[0], c[1], c[2], c[3],
                                al[tm][0], al[tm][1], al[tm][2], al[tm][3],
                                bw[p][half * 2], bw[p][half * 2 + 1]);
                    }
                }
            }
        }
    };

    // ---- GEMM1: A @ Wa ----
    run_gemm(sb + SMEM_W + 0 * ABUF_SZ);
    __syncthreads();

    // ---- epilogue 1: H = split(relu(acc + ba)) -> A buffers ----
    {
        const float* bav = (const float*)(smem + SMEM_BA);
        #pragma unroll
        for (int tm = 0; tm < 2; tm++) {
            #pragma unroll
            for (int tn = 0; tn < 8; tn++) {
                const int col = n0 + tn * 8 + (lane & 3) * 2;
                const float b0v = bav[col], b1v = bav[col + 1];
                const int r_lo = m0 + tm * 16 + (lane >> 2);
                float v0 = fmaxf(acc[tm][tn][0] + b0v, 0.f);
                float v1 = fmaxf(acc[tm][tn][1] + b1v, 0.f);
                float v2 = fmaxf(acc[tm][tn][2] + b0v, 0.f);
                float v3 = fmaxf(acc[tm][tn][3] + b1v, 0.f);
                uint32_t h2, l2;
                split2h(v0, v1, h2, l2);
                *(uint32_t*)(smem + SMEM_AHI + r_lo * PB + col * 2) = h2;
                *(uint32_t*)(smem + SMEM_ALO + r_lo * PB + col * 2) = l2;
                split2h(v2, v3, h2, l2);
                *(uint32_t*)(smem + SMEM_AHI + (r_lo + 8) * PB + col * 2) = h2;
                *(uint32_t*)(smem + SMEM_ALO + (r_lo + 8) * PB + col * 2) = l2;
            }
        }
    }
    __syncthreads();

    // ---- GEMM2: H @ Wb ----
    run_gemm(sb + SMEM_W + 1 * ABUF_SZ);

    // ---- epilogue 2: out = maybe_relu(acc + bb) ----
    {
        const float* bbv = (const float*)(smem + SMEM_BB);
        #pragma unroll
        for (int tm = 0; tm < 2; tm++) {
            #pragma unroll
            for (int tn = 0; tn < 8; tn++) {
                const int col = n0 + tn * 8 + (lane & 3) * 2;
                const float b0v = bbv[col], b1v = bbv[col + 1];
                const int r_lo = row0 + m0 + tm * 16 + (lane >> 2);
                float v0 = acc[tm][tn][0] + b0v;
                float v1 = acc[tm][tn][1] + b1v;
                float v2 = acc[tm][tn][2] + b0v;
                float v3 = acc[tm][tn][3] + b1v;
                if (relu_out) {
                    v0 = fmaxf(v0, 0.f); v1 = fmaxf(v1, 0.f);
                    v2 = fmaxf(v2, 0.f); v3 = fmaxf(v3, 0.f);
                }
                if (r_lo < NNODES)
                    *(float2*)(out + (size_t)r_lo * D + col) = make_float2(v0, v1);
                if (r_lo + 8 < NNODES)
                    *(float2*)(out + (size_t)(r_lo + 8) * D + col) = make_float2(v2, v3);
            }
        }
    }
}

// ---------------------------------------------------------------------------
// launch
// ---------------------------------------------------------------------------
extern "C" void kernel_launch(void* const* d_in, const int* in_sizes, int n_in,
                              void* d_out, int out_size) {
    const float* inputs = (const float*)d_in[0];
    const int*   src    = (const int*)  d_in[1];
    const int*   dst    = (const int*)  d_in[2];
    const float* W1a    = (const float*)d_in[3];
    const float* b1a    = (const float*)d_in[4];
    const float* W1b    = (const float*)d_in[5];
    const float* b1b    = (const float*)d_in[6];
    const float* W2a    = (const float*)d_in[7];
    const float* b2a    = (const float*)d_in[8];
    const float* W2b    = (const float*)d_in[9];
    const float* b2b    = (const float*)d_in[10];
    float* out = (float*)d_out;

    float *gx = nullptr, *gh = nullptr;
    __half* gw = nullptr;
    cudaGetSymbolAddress((void**)&gx, g_x);
    cudaGetSymbolAddress((void**)&gh, g_h);
    cudaGetSymbolAddress((void**)&gw, g_w);

    cudaFuncSetAttribute(k_mlp_hmma, cudaFuncAttributeMaxDynamicSharedMemorySize, SMEM_TOTAL);

    const int edge_blocks = (NEDGES + THREADS - 1) / THREADS;
    const int gath_blocks = (NNODES * 32 + THREADS - 1) / THREADS;
    const int mlp_blocks  = (NNODES + 127) / 128;

    k_hist<<<edge_blocks, THREADS>>>(dst);                        // 0
    k_scanA_wsplit<<<256, 256>>>(W1a, W1b, W2a, W2b);             // 1
    k_scanBC<<<SCAN_BLOCKS, 256>>>();                             // 2
    k_fill<<<edge_blocks, THREADS>>>(src, dst);                   // 3  <- profiled

    // layer 1
    k_gather<<<gath_blocks, THREADS>>>(inputs, gx);               // 4
    k_mlp_hmma<<<mlp_blocks, THREADS, SMEM_TOTAL>>>(              // 5
        gx, gw + 0 * D * D, gw + 1 * D * D, b1a, b1b, gh, 1);

    // layer 2
    k_gather<<<gath_blocks, THREADS>>>(gh, gx);                   // 6
    k_mlp_hmma<<<mlp_blocks, THREADS, SMEM_TOTAL>>>(              // 7
        gx, gw + 2 * D * D, gw + 3 * D * D, b2a, b2b, out, 0);
}

// round 8
// speedup vs baseline: 1.9612x; 1.1373x over previous
#include <cuda_runtime.h>
#include <cuda_fp16.h>
#include <cstdint>

#define D 128
#define NNODES 50000
#define NEDGES 600000
#define THREADS 256
#define SCAN_BLOCKS ((NNODES + 255) / 256)   // 196

// ---------------------------------------------------------------------------
// Device-global scratch (allocation-free rule)
// ---------------------------------------------------------------------------
__device__ float g_x[(size_t)NNODES * D];     // gathered features
__device__ float g_h[(size_t)NNODES * D];     // layer-1 output
__device__ int   g_deg[NNODES];
__device__ int   g_off[NNODES + 1];
__device__ int   g_cursor[NNODES];
__device__ int   g_adj[NEDGES];
__device__ int   g_bsum[256];
// fp16 weights, K-major [n][k], 4 matrices: W1a, W1b, W2a, W2b
__device__ __half g_w[4 * D * D];

// ---------------------------------------------------------------------------
// helpers
// ---------------------------------------------------------------------------
__device__ __forceinline__ uint32_t smem_u32(const void* p) {
    uint32_t a;
    asm("{ .reg .u64 t; cvta.to.shared.u64 t, %1; cvt.u32.u64 %0, t; }" : "=r"(a) : "l"(p));
    return a;
}

__device__ __forceinline__ void ldsm_x4(uint32_t& r0, uint32_t& r1, uint32_t& r2, uint32_t& r3,
                                        uint32_t addr) {
    asm volatile("ldmatrix.sync.aligned.m8n8.x4.shared.b16 {%0,%1,%2,%3}, [%4];"
                 : "=r"(r0), "=r"(r1), "=r"(r2), "=r"(r3) : "r"(addr));
}

__device__ __forceinline__ void mma_f16(float& c0, float& c1, float& c2, float& c3,
                                        uint32_t a0, uint32_t a1, uint32_t a2, uint32_t a3,
                                        uint32_t b0, uint32_t b1) {
    asm volatile("mma.sync.aligned.m16n8k16.row.col.f32.f16.f16.f32 "
                 "{%0,%1,%2,%3}, {%4,%5,%6,%7}, {%8,%9}, {%0,%1,%2,%3};"
                 : "+f"(c0), "+f"(c1), "+f"(c2), "+f"(c3)
                 : "r"(a0), "r"(a1), "r"(a2), "r"(a3), "r"(b0), "r"(b1));
}

__device__ __forceinline__ uint32_t pack2h(float v0, float v1) {
    __half2 h = __floats2half2_rn(v0, v1);
    return *(uint32_t*)&h;
}

// ---------------------------------------------------------------------------
// 0: histogram
// ---------------------------------------------------------------------------
__global__ void k_hist(const int* __restrict__ dst) {
    int e = blockIdx.x * blockDim.x + threadIdx.x;
    if (e < NEDGES) atomicAdd(&g_deg[dst[e]], 1);
}

// ---------------------------------------------------------------------------
// 1: scan phase A (per-256-chunk exclusive scan) + fused weight convert
// ---------------------------------------------------------------------------
__global__ __launch_bounds__(256)
void k_scanA_wsplit(const float* __restrict__ W0, const float* __restrict__ W1,
                    const float* __restrict__ W2, const float* __restrict__ W3) {
    __shared__ int wsum[8];
    const int b = blockIdx.x, tid = threadIdx.x, lane = tid & 31, wd = tid >> 5;

    if (b < SCAN_BLOCKS) {
        int i = b * 256 + tid;
        int v = (i < NNODES) ? g_deg[i] : 0;
        if (i < NNODES) g_deg[i] = 0;            // re-zero for next call
        int s = v;
        #pragma unroll
        for (int o = 1; o < 32; o <<= 1) {
            int t = __shfl_up_sync(0xFFFFFFFFu, s, o);
            if (lane >= o) s += t;
        }
        if (lane == 31) wsum[wd] = s;
        __syncthreads();
        if (wd == 0) {
            int x = (lane < 8) ? wsum[lane] : 0;
            #pragma unroll
            for (int o = 1; o < 8; o <<= 1) {
                int t = __shfl_up_sync(0xFFFFFFFFu, x, o);
                if (lane >= o) x += t;
            }
            if (lane < 8) wsum[lane] = x;
        }
        __syncthreads();
        int excl = (wd ? wsum[wd - 1] : 0) + s - v;
        if (i < NNODES) g_off[i] = excl;
        if (tid == 255) g_bsum[b] = wsum[7];
    }

    // fused weight transpose + fp16 convert: 4*128*128 = 65536 = grid exactly
    {
        int gidx = b * 256 + tid;
        int mat = gidx >> 14;
        int idx = gidx & 16383;
        const float* W = (mat == 0) ? W0 : (mat == 1) ? W1 : (mat == 2) ? W2 : W3;
        int n = idx >> 7, k = idx & 127;
        g_w[gidx] = __float2half_rn(W[k * D + n]);
    }
}

// ---------------------------------------------------------------------------
// 2: scan phase BC
// ---------------------------------------------------------------------------
__global__ __launch_bounds__(256)
void k_scanBC() {
    __shared__ int pre_s;
    __shared__ int wred[8];
    const int b = blockIdx.x, tid = threadIdx.x, lane = tid & 31, wd = tid >> 5;

    int s = 0;
    for (int j = tid; j < b; j += 256) s += g_bsum[j];
    #pragma unroll
    for (int o = 16; o > 0; o >>= 1) s += __shfl_down_sync(0xFFFFFFFFu, s, o);
    if (lane == 0) wred[wd] = s;
    __syncthreads();
    if (tid == 0) {
        int t = 0;
        #pragma unroll
        for (int w = 0; w < 8; w++) t += wred[w];
        pre_s = t;
    }
    __syncthreads();

    int i = b * 256 + tid;
    if (i < NNODES) {
        int off = g_off[i] + pre_s;
        g_off[i] = off;
        g_cursor[i] = off;
    }
    if (b == 0 && tid == 0) g_off[NNODES] = NEDGES;
}

// ---------------------------------------------------------------------------
// 3: fill CSR adjacency
// ---------------------------------------------------------------------------
__global__ void k_fill(const int* __restrict__ src, const int* __restrict__ dst) {
    int e = blockIdx.x * blockDim.x + threadIdx.x;
    if (e < NEDGES) {
        int pos = atomicAdd(&g_cursor[dst[e]], 1);
        g_adj[pos] = src[e];
    }
}

// ---------------------------------------------------------------------------
// gather: x[i] = h[i] + sum_{s in adj(i)} h[s]   (one warp per node)
// ---------------------------------------------------------------------------
__global__ __launch_bounds__(THREADS)
void k_gather(const float* __restrict__ h, float* __restrict__ x) {
    int warp = (blockIdx.x * blockDim.x + threadIdx.x) >> 5;
    int lane = threadIdx.x & 31;
    if (warp >= NNODES) return;
    const float4* hp = (const float4*)h;
    int beg = g_off[warp], end = g_off[warp + 1];
    float4 acc = hp[(size_t)warp * 32 + lane];
    int p = beg;
    for (; p + 4 <= end; p += 4) {
        int s0 = g_adj[p], s1 = g_adj[p + 1], s2 = g_adj[p + 2], s3 = g_adj[p + 3];
        float4 v0 = hp[(size_t)s0 * 32 + lane];
        float4 v1 = hp[(size_t)s1 * 32 + lane];
        float4 v2 = hp[(size_t)s2 * 32 + lane];
        float4 v3 = hp[(size_t)s3 * 32 + lane];
        acc.x += v0.x + v1.x + v2.x + v3.x;
        acc.y += v0.y + v1.y + v2.y + v3.y;
        acc.z += v0.z + v1.z + v2.z + v3.z;
        acc.w += v0.w + v1.w + v2.w + v3.w;
    }
    for (; p < end; ++p) {
        int s = g_adj[p];
        float4 v = hp[(size_t)s * 32 + lane];
        acc.x += v.x; acc.y += v.y; acc.z += v.z; acc.w += v.w;
    }
    ((float4*)x)[(size_t)warp * 32 + lane] = acc;
}

// ---------------------------------------------------------------------------
// HMMA fused MLP (pure fp16): out = maybe_relu( relu(x@Wa+ba) @ Wb + bb )
// A fp16 (single), W fp16. 1 MMA per tile position. 2 CTAs/SM.
// 8 warps, 4(m)x2(n) warp grid, warp tile 32x64.
// ---------------------------------------------------------------------------
#define PB 272
#define SMEM_BA   0
#define SMEM_BB   512
#define SMEM_A    1024
#define ABUF_SZ   (128 * PB)                  // 34816
#define SMEM_W    (SMEM_A + ABUF_SZ)          // 2 x ABUF_SZ: Wa, Wb (fp16)
#define SMEM_TOTAL (SMEM_W + 2 * ABUF_SZ)     // 105472 B -> 2 CTAs/SM

__global__ __launch_bounds__(THREADS, 2)
void k_mlp_hmma(const float* __restrict__ x,
                const __half* __restrict__ wa, const __half* __restrict__ wb,
                const float* __restrict__ ba, const float* __restrict__ bb,
                float* __restrict__ out, int relu_out) {
    extern __shared__ char smem[];
    const uint32_t sb = smem_u32(smem);
    const int tid = threadIdx.x, wid = tid >> 5, lane = tid & 31;
    const int row0 = blockIdx.x * 128;

    // ---- biases ----
    if (tid < 128) {
        ((float*)(smem + SMEM_BA))[tid] = ba[tid];
        ((float*)(smem + SMEM_BB))[tid] = bb[tid];
    }

    // ---- weights -> padded smem (16B chunks); 2 matrices x 2048 chunks ----
    {
        const __half* Wp[2] = {wa, wb};
        #pragma unroll 4
        for (int i = tid; i < 2 * 128 * 16; i += THREADS) {
            int mat = i >> 11;
            int rem = i & 2047;
            int row = rem >> 4;
            int ch  = rem & 15;
            uint4 v = ((const uint4*)Wp[mat])[(row << 4) + ch];
            *(uint4*)(smem + SMEM_W + mat * ABUF_SZ + row * PB + ch * 16) = v;
        }
    }

    // ---- A tile: load fp32, convert to fp16 ----
    {
        int r  = tid >> 1;
        int c0 = (tid & 1) * 64;
        int grow = row0 + r;
        char* ap = smem + SMEM_A + r * PB + c0 * 2;
        if (grow < NNODES) {
            const float4* xp = (const float4*)(x + (size_t)grow * D + c0);
            #pragma unroll
            for (int c = 0; c < 64; c += 4) {
                float4 v = xp[c >> 2];
                *(uint32_t*)(ap + c * 2)     = pack2h(v.x, v.y);
                *(uint32_t*)(ap + c * 2 + 4) = pack2h(v.z, v.w);
            }
        } else {
            #pragma unroll
            for (int c = 0; c < 64; c += 4) {
                *(uint32_t*)(ap + c * 2)     = 0u;
                *(uint32_t*)(ap + c * 2 + 4) = 0u;
            }
        }
    }
    __syncthreads();

    const int warp_m = wid & 3;
    const int warp_n = wid >> 2;
    const int m0 = warp_m * 32;
    const int n0 = warp_n * 64;

    const uint32_t a_off = (uint32_t)((m0 + (lane & 15)) * PB + (lane >> 4) * 16);
    const uint32_t b_off = (uint32_t)((n0 + ((lane >> 4) << 3) + (lane & 7)) * PB
                                      + ((lane >> 3) & 1) * 16);

    const uint32_t Abuf = sb + SMEM_A;

    float acc[2][8][4];

    auto run_gemm = [&](uint32_t Bw) {
        #pragma unroll
        for (int tm = 0; tm < 2; tm++)
            #pragma unroll
            for (int tn = 0; tn < 8; tn++)
                #pragma unroll
                for (int q = 0; q < 4; q++) acc[tm][tn][q] = 0.f;

        #pragma unroll
        for (int s = 0; s < 8; s++) {
            const uint32_t kb = s * 32;
            uint32_t ah[2][4];
            ldsm_x4(ah[0][0], ah[0][1], ah[0][2], ah[0][3], Abuf + a_off + kb);
            ldsm_x4(ah[1][0], ah[1][1], ah[1][2], ah[1][3], Abuf + a_off + 16 * PB + kb);

            uint32_t bw[4][4];
            #pragma unroll
            for (int p = 0; p < 4; p++)
                ldsm_x4(bw[p][0], bw[p][1], bw[p][2], bw[p][3], Bw + b_off + p * 16 * PB + kb);

            #pragma unroll
            for (int tm = 0; tm < 2; tm++) {
                #pragma unroll
                for (int p = 0; p < 4; p++) {
                    #pragma unroll
                    for (int half = 0; half < 2; half++) {
                        const int tn = p * 2 + half;
                        float* c = acc[tm][tn];
                        mma_f16(c[0], c[1], c[2], c[3],
                                ah[tm][0], ah[tm][1], ah[tm][2], ah[tm][3],
                                bw[p][half * 2], bw[p][half * 2 + 1]);
                    }
                }
            }
        }
    };

    // ---- GEMM1: A @ Wa ----
    run_gemm(sb + SMEM_W + 0 * ABUF_SZ);
    __syncthreads();

    // ---- epilogue 1: H = fp16(relu(acc + ba)) -> A buffer ----
    {
        const float* bav = (const float*)(smem + SMEM_BA);
        #pragma unroll
        for (int tm = 0; tm < 2; tm++) {
            #pragma unroll
            for (int tn = 0; tn < 8; tn++) {
                const int col = n0 + tn * 8 + (lane & 3) * 2;
                const float b0v = bav[col], b1v = bav[col + 1];
                const int r_lo = m0 + tm * 16 + (lane >> 2);
                float v0 = fmaxf(acc[tm][tn][0] + b0v, 0.f);
                float v1 = fmaxf(acc[tm][tn][1] + b1v, 0.f);
                float v2 = fmaxf(acc[tm][tn][2] + b0v, 0.f);
                float v3 = fmaxf(acc[tm][tn][3] + b1v, 0.f);
                *(uint32_t*)(smem + SMEM_A + r_lo * PB + col * 2)       = pack2h(v0, v1);
                *(uint32_t*)(smem + SMEM_A + (r_lo + 8) * PB + col * 2) = pack2h(v2, v3);
            }
        }
    }
    __syncthreads();

    // ---- GEMM2: H @ Wb ----
    run_gemm(sb + SMEM_W + 1 * ABUF_SZ);

    // ---- epilogue 2: out = maybe_relu(acc + bb) ----
    {
        const float* bbv = (const float*)(smem + SMEM_BB);
        #pragma unroll
        for (int tm = 0; tm < 2; tm++) {
            #pragma unroll
            for (int tn = 0; tn < 8; tn++) {
                const int col = n0 + tn * 8 + (lane & 3) * 2;
                const float b0v = bbv[col], b1v = bbv[col + 1];
                const int r_lo = row0 + m0 + tm * 16 + (lane >> 2);
                float v0 = acc[tm][tn][0] + b0v;
                float v1 = acc[tm][tn][1] + b1v;
                float v2 = acc[tm][tn][2] + b0v;
                float v3 = acc[tm][tn][3] + b1v;
                if (relu_out) {
                    v0 = fmaxf(v0, 0.f); v1 = fmaxf(v1, 0.f);
                    v2 = fmaxf(v2, 0.f); v3 = fmaxf(v3, 0.f);
                }
                if (r_lo < NNODES)
                    *(float2*)(out + (size_t)r_lo * D + col) = make_float2(v0, v1);
                if (r_lo + 8 < NNODES)
                    *(float2*)(out + (size_t)(r_lo + 8) * D + col) = make_float2(v2, v3);
            }
        }
    }
}

// ---------------------------------------------------------------------------
// launch
// ---------------------------------------------------------------------------
extern "C" void kernel_launch(void* const* d_in, const int* in_sizes, int n_in,
                              void* d_out, int out_size) {
    const float* inputs = (const float*)d_in[0];
    const int*   src    = (const int*)  d_in[1];
    const int*   dst    = (const int*)  d_in[2];
    const float* W1a    = (const float*)d_in[3];
    const float* b1a    = (const float*)d_in[4];
    const float* W1b    = (const float*)d_in[5];
    const float* b1b    = (const float*)d_in[6];
    const float* W2a    = (const float*)d_in[7];
    const float* b2a    = (const float*)d_in[8];
    const float* W2b    = (const float*)d_in[9];
    const float* b2b    = (const float*)d_in[10];
    float* out = (float*)d_out;

    float *gx = nullptr, *gh = nullptr;
    __half* gw = nullptr;
    cudaGetSymbolAddress((void**)&gx, g_x);
    cudaGetSymbolAddress((void**)&gh, g_h);
    cudaGetSymbolAddress((void**)&gw, g_w);

    cudaFuncSetAttribute(k_mlp_hmma, cudaFuncAttributeMaxDynamicSharedMemorySize, SMEM_TOTAL);

    const int edge_blocks = (NEDGES + THREADS - 1) / THREADS;
    const int gath_blocks = (NNODES * 32 + THREADS - 1) / THREADS;
    const int mlp_blocks  = (NNODES + 127) / 128;

    k_hist<<<edge_blocks, THREADS>>>(dst);                        // 0
    k_scanA_wsplit<<<256, 256>>>(W1a, W1b, W2a, W2b);             // 1
    k_scanBC<<<SCAN_BLOCKS, 256>>>();                             // 2
    k_fill<<<edge_blocks, THREADS>>>(src, dst);                   // 3  <- profiled

    // layer 1
    k_gather<<<gath_blocks, THREADS>>>(inputs, gx);               // 4
    k_mlp_hmma<<<mlp_blocks, THREADS, SMEM_TOTAL>>>(              // 5
        gx, gw + 0 * D * D, gw + 1 * D * D, b1a, b1b, gh, 1);

    // layer 2
    k_gather<<<gath_blocks, THREADS>>>(gh, gx);                   // 6
    k_mlp_hmma<<<mlp_blocks, THREADS, SMEM_TOTAL>>>(              // 7
        gx, gw + 2 * D * D, gw + 3 * D * D, b2a, b2b, out, 0);
}

// round 9
// speedup vs baseline: 2.2739x; 1.1594x over previous
#include <cuda_runtime.h>
#include <cuda_fp16.h>
#include <cstdint>

#define D 128
#define NNODES 50000
#define NEDGES 600000
#define THREADS 256
#define SCAN_BLOCKS ((NNODES + 255) / 256)   // 196

// ---------------------------------------------------------------------------
// Device-global scratch (allocation-free rule)
// ---------------------------------------------------------------------------
__device__ __half g_inh[(size_t)NNODES * D];  // fp16 copy of inputs
__device__ __half g_xh[(size_t)NNODES * D];   // gathered features (fp16)
__device__ __half g_hh[(size_t)NNODES * D];   // layer-1 output (fp16)
__device__ int   g_deg[NNODES];
__device__ int   g_off[NNODES + 1];
__device__ int   g_cursor[NNODES];
__device__ int   g_adj[NEDGES];
__device__ int   g_bsum[256];
// fp16 weights, K-major [n][k], 4 matrices: W1a, W1b, W2a, W2b
__device__ __half g_w[4 * D * D];

// ---------------------------------------------------------------------------
// helpers
// ---------------------------------------------------------------------------
__device__ __forceinline__ uint32_t smem_u32(const void* p) {
    uint32_t a;
    asm("{ .reg .u64 t; cvta.to.shared.u64 t, %1; cvt.u32.u64 %0, t; }" : "=r"(a) : "l"(p));
    return a;
}

__device__ __forceinline__ void ldsm_x4(uint32_t& r0, uint32_t& r1, uint32_t& r2, uint32_t& r3,
                                        uint32_t addr) {
    asm volatile("ldmatrix.sync.aligned.m8n8.x4.shared.b16 {%0,%1,%2,%3}, [%4];"
                 : "=r"(r0), "=r"(r1), "=r"(r2), "=r"(r3) : "r"(addr));
}

__device__ __forceinline__ void mma_f16(float& c0, float& c1, float& c2, float& c3,
                                        uint32_t a0, uint32_t a1, uint32_t a2, uint32_t a3,
                                        uint32_t b0, uint32_t b1) {
    asm volatile("mma.sync.aligned.m16n8k16.row.col.f32.f16.f16.f32 "
                 "{%0,%1,%2,%3}, {%4,%5,%6,%7}, {%8,%9}, {%0,%1,%2,%3};"
                 : "+f"(c0), "+f"(c1), "+f"(c2), "+f"(c3)
                 : "r"(a0), "r"(a1), "r"(a2), "r"(a3), "r"(b0), "r"(b1));
}

__device__ __forceinline__ uint32_t pack2h(float v0, float v1) {
    __half2 h = __floats2half2_rn(v0, v1);
    return *(uint32_t*)&h;
}

__device__ __forceinline__ float2 h2f(uint32_t u) {
    __half2 h = *(__half2*)&u;
    return __half22float2(h);
}

// ---------------------------------------------------------------------------
// 0: histogram + fused fp32->fp16 input conversion
// ---------------------------------------------------------------------------
__global__ void k_hist_cvt(const int* __restrict__ dst, const float* __restrict__ inputs) {
    int gid = blockIdx.x * blockDim.x + threadIdx.x;
    if (gid < NEDGES) atomicAdd(&g_deg[dst[gid]], 1);
    // convert inputs: NNODES*D/4 = 1.6M float4 -> uint2(4 halves)
    const int total = NNODES * D / 4;
    const int stride = gridDim.x * blockDim.x;
    for (int i = gid; i < total; i += stride) {
        float4 v = ((const float4*)inputs)[i];
        uint2 o;
        o.x = pack2h(v.x, v.y);
        o.y = pack2h(v.z, v.w);
        ((uint2*)g_inh)[i] = o;
    }
}

// ---------------------------------------------------------------------------
// 1: scan phase A (per-256-chunk exclusive scan) + fused weight convert
// ---------------------------------------------------------------------------
__global__ __launch_bounds__(256)
void k_scanA_wsplit(const float* __restrict__ W0, const float* __restrict__ W1,
                    const float* __restrict__ W2, const float* __restrict__ W3) {
    __shared__ int wsum[8];
    const int b = blockIdx.x, tid = threadIdx.x, lane = tid & 31, wd = tid >> 5;

    if (b < SCAN_BLOCKS) {
        int i = b * 256 + tid;
        int v = (i < NNODES) ? g_deg[i] : 0;
        if (i < NNODES) g_deg[i] = 0;            // re-zero for next call
        int s = v;
        #pragma unroll
        for (int o = 1; o < 32; o <<= 1) {
            int t = __shfl_up_sync(0xFFFFFFFFu, s, o);
            if (lane >= o) s += t;
        }
        if (lane == 31) wsum[wd] = s;
        __syncthreads();
        if (wd == 0) {
            int x = (lane < 8) ? wsum[lane] : 0;
            #pragma unroll
            for (int o = 1; o < 8; o <<= 1) {
                int t = __shfl_up_sync(0xFFFFFFFFu, x, o);
                if (lane >= o) x += t;
            }
            if (lane < 8) wsum[lane] = x;
        }
        __syncthreads();
        int excl = (wd ? wsum[wd - 1] : 0) + s - v;
        if (i < NNODES) g_off[i] = excl;
        if (tid == 255) g_bsum[b] = wsum[7];
    }

    // fused weight transpose + fp16 convert: 4*128*128 = 65536 = grid exactly
    {
        int gidx = b * 256 + tid;
        int mat = gidx >> 14;
        int idx = gidx & 16383;
        const float* W = (mat == 0) ? W0 : (mat == 1) ? W1 : (mat == 2) ? W2 : W3;
        int n = idx >> 7, k = idx & 127;
        g_w[gidx] = __float2half_rn(W[k * D + n]);
    }
}

// ---------------------------------------------------------------------------
// 2: scan phase BC
// ---------------------------------------------------------------------------
__global__ __launch_bounds__(256)
void k_scanBC() {
    __shared__ int pre_s;
    __shared__ int wred[8];
    const int b = blockIdx.x, tid = threadIdx.x, lane = tid & 31, wd = tid >> 5;

    int s = 0;
    for (int j = tid; j < b; j += 256) s += g_bsum[j];
    #pragma unroll
    for (int o = 16; o > 0; o >>= 1) s += __shfl_down_sync(0xFFFFFFFFu, s, o);
    if (lane == 0) wred[wd] = s;
    __syncthreads();
    if (tid == 0) {
        int t = 0;
        #pragma unroll
        for (int w = 0; w < 8; w++) t += wred[w];
        pre_s = t;
    }
    __syncthreads();

    int i = b * 256 + tid;
    if (i < NNODES) {
        int off = g_off[i] + pre_s;
        g_off[i] = off;
        g_cursor[i] = off;
    }
    if (b == 0 && tid == 0) g_off[NNODES] = NEDGES;
}

// ---------------------------------------------------------------------------
// 3: fill CSR adjacency
// ---------------------------------------------------------------------------
__global__ void k_fill(const int* __restrict__ src, const int* __restrict__ dst) {
    int e = blockIdx.x * blockDim.x + threadIdx.x;
    if (e < NEDGES) {
        int pos = atomicAdd(&g_cursor[dst[e]], 1);
        g_adj[pos] = src[e];
    }
}

// ---------------------------------------------------------------------------
// gather (fp16): x[i] = h[i] + sum_{s in adj(i)} h[s]
// one warp per node; lane owns 4 halves (8B). fp32 accumulation.
// ---------------------------------------------------------------------------
__global__ __launch_bounds__(THREADS)
void k_gather_h(const __half* __restrict__ h, __half* __restrict__ x) {
    int warp = (blockIdx.x * blockDim.x + threadIdx.x) >> 5;
    int lane = threadIdx.x & 31;
    if (warp >= NNODES) return;
    const uint2* hp = (const uint2*)h;
    int beg = g_off[warp], end = g_off[warp + 1];

    uint2 self = hp[(size_t)warp * 32 + lane];
    float2 a0 = h2f(self.x), a1 = h2f(self.y);
    float acc0 = a0.x, acc1 = a0.y, acc2 = a1.x, acc3 = a1.y;

    int p = beg;
    for (; p + 4 <= end; p += 4) {
        int s0 = g_adj[p], s1 = g_adj[p + 1], s2 = g_adj[p + 2], s3 = g_adj[p + 3];
        uint2 v0 = hp[(size_t)s0 * 32 + lane];
        uint2 v1 = hp[(size_t)s1 * 32 + lane];
        uint2 v2 = hp[(size_t)s2 * 32 + lane];
        uint2 v3 = hp[(size_t)s3 * 32 + lane];
        float2 f;
        f = h2f(v0.x); acc0 += f.x; acc1 += f.y;
        f = h2f(v0.y); acc2 += f.x; acc3 += f.y;
        f = h2f(v1.x); acc0 += f.x; acc1 += f.y;
        f = h2f(v1.y); acc2 += f.x; acc3 += f.y;
        f = h2f(v2.x); acc0 += f.x; acc1 += f.y;
        f = h2f(v2.y); acc2 += f.x; acc3 += f.y;
        f = h2f(v3.x); acc0 += f.x; acc1 += f.y;
        f = h2f(v3.y); acc2 += f.x; acc3 += f.y;
    }
    for (; p < end; ++p) {
        int s = g_adj[p];
        uint2 v = hp[(size_t)s * 32 + lane];
        float2 f;
        f = h2f(v.x); acc0 += f.x; acc1 += f.y;
        f = h2f(v.y); acc2 += f.x; acc3 += f.y;
    }
    uint2 o;
    o.x = pack2h(acc0, acc1);
    o.y = pack2h(acc2, acc3);
    ((uint2*)x)[(size_t)warp * 32 + lane] = o;
}

// ---------------------------------------------------------------------------
// HMMA fused MLP (pure fp16): out = maybe_relu( relu(x@Wa+ba) @ Wb + bb )
// A fp16 in gmem already. OUT_HALF selects fp16 (layer 1) vs fp32 (layer 2) out.
// 8 warps, 4(m)x2(n) warp grid, warp tile 32x64. 2 CTAs/SM.
// ---------------------------------------------------------------------------
#define PB 272
#define SMEM_BA   0
#define SMEM_BB   512
#define SMEM_A    1024
#define ABUF_SZ   (128 * PB)                  // 34816
#define SMEM_W    (SMEM_A + ABUF_SZ)          // 2 x ABUF_SZ: Wa, Wb (fp16)
#define SMEM_TOTAL (SMEM_W + 2 * ABUF_SZ)     // 105472 B -> 2 CTAs/SM

template <int OUT_HALF>
__global__ __launch_bounds__(THREADS, 2)
void k_mlp_hmma(const __half* __restrict__ x,
                const __half* __restrict__ wa, const __half* __restrict__ wb,
                const float* __restrict__ ba, const float* __restrict__ bb,
                void* __restrict__ outp, int relu_out) {
    extern __shared__ char smem[];
    const uint32_t sb = smem_u32(smem);
    const int tid = threadIdx.x, wid = tid >> 5, lane = tid & 31;
    const int row0 = blockIdx.x * 128;

    // ---- biases ----
    if (tid < 128) {
        ((float*)(smem + SMEM_BA))[tid] = ba[tid];
        ((float*)(smem + SMEM_BB))[tid] = bb[tid];
    }

    // ---- weights -> padded smem (16B chunks); 2 matrices x 2048 chunks ----
    {
        const __half* Wp[2] = {wa, wb};
        #pragma unroll 4
        for (int i = tid; i < 2 * 128 * 16; i += THREADS) {
            int mat = i >> 11;
            int rem = i & 2047;
            int row = rem >> 4;
            int ch  = rem & 15;
            uint4 v = ((const uint4*)Wp[mat])[(row << 4) + ch];
            *(uint4*)(smem + SMEM_W + mat * ABUF_SZ + row * PB + ch * 16) = v;
        }
    }

    // ---- A tile: straight fp16 copy (128 rows x 256B) ----
    {
        int r  = tid >> 1;
        int c0 = (tid & 1) * 128;                 // byte offset within row: 0 or 128
        int grow = row0 + r;
        char* ap = smem + SMEM_A + r * PB + c0;
        if (grow < NNODES) {
            const char* xp = (const char*)(x + (size_t)grow * D) + c0;
            #pragma unroll
            for (int c = 0; c < 128; c += 16)
                *(uint4*)(ap + c) = *(const uint4*)(xp + c);
        } else {
            #pragma unroll
            for (int c = 0; c < 128; c += 16)
                *(uint4*)(ap + c) = make_uint4(0u, 0u, 0u, 0u);
        }
    }
    __syncthreads();

    const int warp_m = wid & 3;
    const int warp_n = wid >> 2;
    const int m0 = warp_m * 32;
    const int n0 = warp_n * 64;

    const uint32_t a_off = (uint32_t)((m0 + (lane & 15)) * PB + (lane >> 4) * 16);
    const uint32_t b_off = (uint32_t)((n0 + ((lane >> 4) << 3) + (lane & 7)) * PB
                                      + ((lane >> 3) & 1) * 16);

    const uint32_t Abuf = sb + SMEM_A;

    float acc[2][8][4];

    auto run_gemm = [&](uint32_t Bw) {
        #pragma unroll
        for (int tm = 0; tm < 2; tm++)
            #pragma unroll
            for (int tn = 0; tn < 8; tn++)
                #pragma unroll
                for (int q = 0; q < 4; q++) acc[tm][tn][q] = 0.f;

        #pragma unroll
        for (int s = 0; s < 8; s++) {
            const uint32_t kb = s * 32;
            uint32_t ah[2][4];
            ldsm_x4(ah[0][0], ah[0][1], ah[0][2], ah[0][3], Abuf + a_off + kb);
            ldsm_x4(ah[1][0], ah[1][1], ah[1][2], ah[1][3], Abuf + a_off + 16 * PB + kb);

            uint32_t bw[4][4];
            #pragma unroll
            for (int p = 0; p < 4; p++)
                ldsm_x4(bw[p][0], bw[p][1], bw[p][2], bw[p][3], Bw + b_off + p * 16 * PB + kb);

            #pragma unroll
            for (int tm = 0; tm < 2; tm++) {
                #pragma unroll
                for (int p = 0; p < 4; p++) {
                    #pragma unroll
                    for (int half = 0; half < 2; half++) {
                        const int tn = p * 2 + half;
                        float* c = acc[tm][tn];
                        mma_f16(c[0], c[1], c[2], c[3],
                                ah[tm][0], ah[tm][1], ah[tm][2], ah[tm][3],
                                bw[p][half * 2], bw[p][half * 2 + 1]);
                    }
                }
            }
        }
    };

    // ---- GEMM1: A @ Wa ----
    run_gemm(sb + SMEM_W + 0 * ABUF_SZ);
    __syncthreads();

    // ---- epilogue 1: H = fp16(relu(acc + ba)) -> A buffer ----
    {
        const float* bav = (const float*)(smem + SMEM_BA);
        #pragma unroll
        for (int tm = 0; tm < 2; tm++) {
            #pragma unroll
            for (int tn = 0; tn < 8; tn++) {
                const int col = n0 + tn * 8 + (lane & 3) * 2;
                const float b0v = bav[col], b1v = bav[col + 1];
                const int r_lo = m0 + tm * 16 + (lane >> 2);
                float v0 = fmaxf(acc[tm][tn][0] + b0v, 0.f);
                float v1 = fmaxf(acc[tm][tn][1] + b1v, 0.f);
                float v2 = fmaxf(acc[tm][tn][2] + b0v, 0.f);
                float v3 = fmaxf(acc[tm][tn][3] + b1v, 0.f);
                *(uint32_t*)(smem + SMEM_A + r_lo * PB + col * 2)       = pack2h(v0, v1);
                *(uint32_t*)(smem + SMEM_A + (r_lo + 8) * PB + col * 2) = pack2h(v2, v3);
            }
        }
    }
    __syncthreads();

    // ---- GEMM2: H @ Wb ----
    run_gemm(sb + SMEM_W + 1 * ABUF_SZ);

    // ---- epilogue 2 ----
    {
        const float* bbv = (const float*)(smem + SMEM_BB);
        #pragma unroll
        for (int tm = 0; tm < 2; tm++) {
            #pragma unroll
            for (int tn = 0; tn < 8; tn++) {
                const int col = n0 + tn * 8 + (lane & 3) * 2;
                const float b0v = bbv[col], b1v = bbv[col + 1];
                const int r_lo = row0 + m0 + tm * 16 + (lane >> 2);
                float v0 = acc[tm][tn][0] + b0v;
                float v1 = acc[tm][tn][1] + b1v;
                float v2 = acc[tm][tn][2] + b0v;
                float v3 = acc[tm][tn][3] + b1v;
                if (relu_out) {
                    v0 = fmaxf(v0, 0.f); v1 = fmaxf(v1, 0.f);
                    v2 = fmaxf(v2, 0.f); v3 = fmaxf(v3, 0.f);
                }
                if (OUT_HALF) {
                    __half* out = (__half*)outp;
                    if (r_lo < NNODES)
                        *(uint32_t*)(out + (size_t)r_lo * D + col) = pack2h(v0, v1);
                    if (r_lo + 8 < NNODES)
                        *(uint32_t*)(out + (size_t)(r_lo + 8) * D + col) = pack2h(v2, v3);
                } else {
                    float* out = (float*)outp;
                    if (r_lo < NNODES)
                        *(float2*)(out + (size_t)r_lo * D + col) = make_float2(v0, v1);
                    if (r_lo + 8 < NNODES)
                        *(float2*)(out + (size_t)(r_lo + 8) * D + col) = make_float2(v2, v3);
                }
            }
        }
    }
}

// ---------------------------------------------------------------------------
// launch
// ---------------------------------------------------------------------------
extern "C" void kernel_launch(void* const* d_in, const int* in_sizes, int n_in,
                              void* d_out, int out_size) {
    const float* inputs = (const float*)d_in[0];
    const int*   src    = (const int*)  d_in[1];
    const int*   dst    = (const int*)  d_in[2];
    const float* W1a    = (const float*)d_in[3];
    const float* b1a    = (const float*)d_in[4];
    const float* W1b    = (const float*)d_in[5];
    const float* b1b    = (const float*)d_in[6];
    const float* W2a    = (const float*)d_in[7];
    const float* b2a    = (const float*)d_in[8];
    const float* W2b    = (const float*)d_in[9];
    const float* b2b    = (const float*)d_in[10];

    __half *ginh = nullptr, *gxh = nullptr, *ghh = nullptr, *gw = nullptr;
    cudaGetSymbolAddress((void**)&ginh, g_inh);
    cudaGetSymbolAddress((void**)&gxh, g_xh);
    cudaGetSymbolAddress((void**)&ghh, g_hh);
    cudaGetSymbolAddress((void**)&gw, g_w);

    cudaFuncSetAttribute(k_mlp_hmma<1>, cudaFuncAttributeMaxDynamicSharedMemorySize, SMEM_TOTAL);
    cudaFuncSetAttribute(k_mlp_hmma<0>, cudaFuncAttributeMaxDynamicSharedMemorySize, SMEM_TOTAL);

    const int edge_blocks = (NEDGES + THREADS - 1) / THREADS;
    const int gath_blocks = (NNODES * 32 + THREADS - 1) / THREADS;
    const int mlp_blocks  = (NNODES + 127) / 128;

    k_hist_cvt<<<edge_blocks, THREADS>>>(dst, inputs);            // 0
    k_scanA_wsplit<<<256, 256>>>(W1a, W1b, W2a, W2b);             // 1
    k_scanBC<<<SCAN_BLOCKS, 256>>>();                             // 2
    k_fill<<<edge_blocks, THREADS>>>(src, dst);                   // 3  <- profiled

    // layer 1
    k_gather_h<<<gath_blocks, THREADS>>>(ginh, gxh);              // 4
    k_mlp_hmma<1><<<mlp_blocks, THREADS, SMEM_TOTAL>>>(           // 5
        gxh, gw + 0 * D * D, gw + 1 * D * D, b1a, b1b, ghh, 1);

    // layer 2
    k_gather_h<<<gath_blocks, THREADS>>>(ghh, gxh);               // 6
    k_mlp_hmma<0><<<mlp_blocks, THREADS, SMEM_TOTAL>>>(           // 7
        gxh, gw + 2 * D * D, gw + 3 * D * D, b2a, b2b, d_out, 0);
}

// round 11
// speedup vs baseline: 2.3038x; 1.0132x over previous
#include <cuda_runtime.h>
#include <cuda_fp16.h>
#include <cstdint>

#define D 128
#define NNODES 50000
#define NEDGES 600000
#define THREADS 256
#define SCAN_BLOCKS ((NNODES + 255) / 256)   // 196

// ---------------------------------------------------------------------------
// Device-global scratch (allocation-free rule)
// ---------------------------------------------------------------------------
__device__ __half g_inh[(size_t)NNODES * D];  // fp16 copy of inputs
__device__ __half g_xh[(size_t)NNODES * D];   // gathered features (fp16)
__device__ __half g_hh[(size_t)NNODES * D];   // layer-1 output (fp16)
__device__ int   g_deg[NNODES];
__device__ int   g_off[NNODES + 1];
__device__ int   g_cursor[NNODES];
__device__ int   g_adj[NEDGES];
__device__ int   g_bsum[256];
// fp16 weights, K-major [n][k], 4 matrices: W1a, W1b, W2a, W2b
__device__ __half g_w[4 * D * D];

// ---------------------------------------------------------------------------
// helpers
// ---------------------------------------------------------------------------
__device__ __forceinline__ uint32_t smem_u32(const void* p) {
    uint32_t a;
    asm("{ .reg .u64 t; cvta.to.shared.u64 t, %1; cvt.u32.u64 %0, t; }" : "=r"(a) : "l"(p));
    return a;
}

__device__ __forceinline__ void ldsm_x4(uint32_t& r0, uint32_t& r1, uint32_t& r2, uint32_t& r3,
                                        uint32_t addr) {
    asm volatile("ldmatrix.sync.aligned.m8n8.x4.shared.b16 {%0,%1,%2,%3}, [%4];"
                 : "=r"(r0), "=r"(r1), "=r"(r2), "=r"(r3) : "r"(addr));
}

__device__ __forceinline__ void mma_f16(float& c0, float& c1, float& c2, float& c3,
                                        uint32_t a0, uint32_t a1, uint32_t a2, uint32_t a3,
                                        uint32_t b0, uint32_t b1) {
    asm volatile("mma.sync.aligned.m16n8k16.row.col.f32.f16.f16.f32 "
                 "{%0,%1,%2,%3}, {%4,%5,%6,%7}, {%8,%9}, {%0,%1,%2,%3};"
                 : "+f"(c0), "+f"(c1), "+f"(c2), "+f"(c3)
                 : "r"(a0), "r"(a1), "r"(a2), "r"(a3), "r"(b0), "r"(b1));
}

__device__ __forceinline__ uint32_t pack2h(float v0, float v1) {
    __half2 h = __floats2half2_rn(v0, v1);
    return *(uint32_t*)&h;
}

__device__ __forceinline__ float2 h2f(uint32_t u) {
    __half2 h = *(__half2*)&u;
    return __half22float2(h);
}

// ---------------------------------------------------------------------------
// 0: histogram + fused fp32->fp16 input conversion
// ---------------------------------------------------------------------------
__global__ void k_hist_cvt(const int* __restrict__ dst, const float* __restrict__ inputs) {
    int gid = blockIdx.x * blockDim.x + threadIdx.x;
    if (gid < NEDGES) atomicAdd(&g_deg[dst[gid]], 1);
    const int total = NNODES * D / 4;
    const int stride = gridDim.x * blockDim.x;
    for (int i = gid; i < total; i += stride) {
        float4 v = ((const float4*)inputs)[i];
        uint2 o;
        o.x = pack2h(v.x, v.y);
        o.y = pack2h(v.z, v.w);
        ((uint2*)g_inh)[i] = o;
    }
}

// ---------------------------------------------------------------------------
// 1: scan phase A (per-256-chunk exclusive scan) + fused weight convert
// ---------------------------------------------------------------------------
__global__ __launch_bounds__(256)
void k_scanA_wsplit(const float* __restrict__ W0, const float* __restrict__ W1,
                    const float* __restrict__ W2, const float* __restrict__ W3) {
    __shared__ int wsum[8];
    const int b = blockIdx.x, tid = threadIdx.x, lane = tid & 31, wd = tid >> 5;

    if (b < SCAN_BLOCKS) {
        int i = b * 256 + tid;
        int v = (i < NNODES) ? g_deg[i] : 0;
        if (i < NNODES) g_deg[i] = 0;            // re-zero for next call
        int s = v;
        #pragma unroll
        for (int o = 1; o < 32; o <<= 1) {
            int t = __shfl_up_sync(0xFFFFFFFFu, s, o);
            if (lane >= o) s += t;
        }
        if (lane == 31) wsum[wd] = s;
        __syncthreads();
        if (wd == 0) {
            int x = (lane < 8) ? wsum[lane] : 0;
            #pragma unroll
            for (int o = 1; o < 8; o <<= 1) {
                int t = __shfl_up_sync(0xFFFFFFFFu, x, o);
                if (lane >= o) x += t;
            }
            if (lane < 8) wsum[lane] = x;
        }
        __syncthreads();
        int excl = (wd ? wsum[wd - 1] : 0) + s - v;
        if (i < NNODES) g_off[i] = excl;
        if (tid == 255) g_bsum[b] = wsum[7];
    }

    // fused weight transpose + fp16 convert: 4*128*128 = 65536 = grid exactly
    {
        int gidx = b * 256 + tid;
        int mat = gidx >> 14;
        int idx = gidx & 16383;
        const float* W = (mat == 0) ? W0 : (mat == 1) ? W1 : (mat == 2) ? W2 : W3;
        int n = idx >> 7, k = idx & 127;
        g_w[gidx] = __float2half_rn(W[k * D + n]);
    }
}

// ---------------------------------------------------------------------------
// 2: scan phase BC
// ---------------------------------------------------------------------------
__global__ __launch_bounds__(256)
void k_scanBC() {
    __shared__ int pre_s;
    __shared__ int wred[8];
    const int b = blockIdx.x, tid = threadIdx.x, lane = tid & 31, wd = tid >> 5;

    int s = 0;
    for (int j = tid; j < b; j += 256) s += g_bsum[j];
    #pragma unroll
    for (int o = 16; o > 0; o >>= 1) s += __shfl_down_sync(0xFFFFFFFFu, s, o);
    if (lane == 0) wred[wd] = s;
    __syncthreads();
    if (tid == 0) {
        int t = 0;
        #pragma unroll
        for (int w = 0; w < 8; w++) t += wred[w];
        pre_s = t;
    }
    __syncthreads();

    int i = b * 256 + tid;
    if (i < NNODES) {
        int off = g_off[i] + pre_s;
        g_off[i] = off;
        g_cursor[i] = off;
    }
    if (b == 0 && tid == 0) g_off[NNODES] = NEDGES;
}

// ---------------------------------------------------------------------------
// 3: fill CSR adjacency
// ---------------------------------------------------------------------------
__global__ void k_fill(const int* __restrict__ src, const int* __restrict__ dst) {
    int e = blockIdx.x * blockDim.x + threadIdx.x;
    if (e < NEDGES) {
        int pos = atomicAdd(&g_cursor[dst[e]], 1);
        g_adj[pos] = src[e];
    }
}

// ---------------------------------------------------------------------------
// gather (fp16): x[i] = h[i] + sum_{s in adj(i)} h[s]
// ---------------------------------------------------------------------------
__global__ __launch_bounds__(THREADS)
void k_gather_h(const __half* __restrict__ h, __half* __restrict__ x) {
    int warp = (blockIdx.x * blockDim.x + threadIdx.x) >> 5;
    int lane = threadIdx.x & 31;
    if (warp >= NNODES) return;
    const uint2* hp = (const uint2*)h;
    int beg = g_off[warp], end = g_off[warp + 1];

    uint2 self = hp[(size_t)warp * 32 + lane];
    float2 a0 = h2f(self.x), a1 = h2f(self.y);
    float acc0 = a0.x, acc1 = a0.y, acc2 = a1.x, acc3 = a1.y;

    int p = beg;
    for (; p + 4 <= end; p += 4) {
        int s0 = g_adj[p], s1 = g_adj[p + 1], s2 = g_adj[p + 2], s3 = g_adj[p + 3];
        uint2 v0 = hp[(size_t)s0 * 32 + lane];
        uint2 v1 = hp[(size_t)s1 * 32 + lane];
        uint2 v2 = hp[(size_t)s2 * 32 + lane];
        uint2 v3 = hp[(size_t)s3 * 32 + lane];
        float2 f;
        f = h2f(v0.x); acc0 += f.x; acc1 += f.y;
        f = h2f(v0.y); acc2 += f.x; acc3 += f.y;
        f = h2f(v1.x); acc0 += f.x; acc1 += f.y;
        f = h2f(v1.y); acc2 += f.x; acc3 += f.y;
        f = h2f(v2.x); acc0 += f.x; acc1 += f.y;
        f = h2f(v2.y); acc2 += f.x; acc3 += f.y;
        f = h2f(v3.x); acc0 += f.x; acc1 += f.y;
        f = h2f(v3.y); acc2 += f.x; acc3 += f.y;
    }
    for (; p < end; ++p) {
        int s = g_adj[p];
        uint2 v = hp[(size_t)s * 32 + lane];
        float2 f;
        f = h2f(v.x); acc0 += f.x; acc1 += f.y;
        f = h2f(v.y); acc2 += f.x; acc3 += f.y;
    }
    uint2 o;
    o.x = pack2h(acc0, acc1);
    o.y = pack2h(acc2, acc3);
    ((uint2*)x)[(size_t)warp * 32 + lane] = o;
}

// ---------------------------------------------------------------------------
// HMMA fused MLP (pure fp16, staged weights): 3 CTAs/SM, single wave.
// Wa -> GEMM1 -> (epi1 + load Wb over Wa) -> GEMM2.
// 8 warps, 4(m)x2(n) warp grid, warp tile 32x64.
// ---------------------------------------------------------------------------
#define PB 272
#define SMEM_BA   0
#define SMEM_BB   512
#define SMEM_A    1024
#define ABUF_SZ   (128 * PB)                  // 34816
#define SMEM_W    (SMEM_A + ABUF_SZ)          // ONE weight matrix at a time
#define SMEM_TOTAL (SMEM_W + ABUF_SZ)         // 70656 B -> 3 CTAs/SM

template <int OUT_HALF>
__global__ __launch_bounds__(THREADS, 3)
void k_mlp_hmma(const __half* __restrict__ x,
                const __half* __restrict__ wa, const __half* __restrict__ wb,
                const float* __restrict__ ba, const float* __restrict__ bb,
                void* __restrict__ outp, int relu_out) {
    extern __shared__ char smem[];
    const uint32_t sb = smem_u32(smem);
    const int tid = threadIdx.x, wid = tid >> 5, lane = tid & 31;
    const int row0 = blockIdx.x * 128;

    // ---- biases ----
    if (tid < 128) {
        ((float*)(smem + SMEM_BA))[tid] = ba[tid];
        ((float*)(smem + SMEM_BB))[tid] = bb[tid];
    }

    // ---- Wa -> padded smem (2048 x 16B chunks); rolled to cap reg pressure ----
    #pragma unroll 1
    for (int i = tid; i < 128 * 16; i += THREADS) {
        int row = i >> 4, ch = i & 15;
        uint4 v = ((const uint4*)wa)[(row << 4) + ch];
        *(uint4*)(smem + SMEM_W + row * PB + ch * 16) = v;
    }

    // ---- A tile: straight fp16 copy (128 rows x 256B) ----
    {
        int r  = tid >> 1;
        int c0 = (tid & 1) * 128;
        int grow = row0 + r;
        char* ap = smem + SMEM_A + r * PB + c0;
        if (grow < NNODES) {
            const char* xp = (const char*)(x + (size_t)grow * D) + c0;
            #pragma unroll
            for (int c = 0; c < 128; c += 16)
                *(uint4*)(ap + c) = *(const uint4*)(xp + c);
        } else {
            #pragma unroll
            for (int c = 0; c < 128; c += 16)
                *(uint4*)(ap + c) = make_uint4(0u, 0u, 0u, 0u);
        }
    }
    __syncthreads();

    const int warp_m = wid & 3;
    const int warp_n = wid >> 2;
    const int m0 = warp_m * 32;
    const int n0 = warp_n * 64;

    const uint32_t a_off = (uint32_t)((m0 + (lane & 15)) * PB + (lane >> 4) * 16);
    const uint32_t b_off = (uint32_t)((n0 + ((lane >> 4) << 3) + (lane & 7)) * PB
                                      + ((lane >> 3) & 1) * 16);

    const uint32_t Abuf = sb + SMEM_A;
    const uint32_t Wbuf = sb + SMEM_W;

    float acc[2][8][4];

    // per-p B-fragment loads: only 4 bw regs live at a time (reg budget 85 @ occ 3)
    auto run_gemm = [&]() {
        #pragma unroll
        for (int tm = 0; tm < 2; tm++)
            #pragma unroll
            for (int tn = 0; tn < 8; tn++)
                #pragma unroll
                for (int q = 0; q < 4; q++) acc[tm][tn][q] = 0.f;

        #pragma unroll
        for (int s = 0; s < 8; s++) {
            const uint32_t kb = s * 32;
            uint32_t ah[2][4];
            ldsm_x4(ah[0][0], ah[0][1], ah[0][2], ah[0][3], Abuf + a_off + kb);
            ldsm_x4(ah[1][0], ah[1][1], ah[1][2], ah[1][3], Abuf + a_off + 16 * PB + kb);

            #pragma unroll
            for (int p = 0; p < 4; p++) {
                uint32_t b0, b1, b2, b3;
                ldsm_x4(b0, b1, b2, b3, Wbuf + b_off + p * 16 * PB + kb);
                #pragma unroll
                for (int tm = 0; tm < 2; tm++) {
                    float* c0 = acc[tm][p * 2];
                    float* c1 = acc[tm][p * 2 + 1];
                    mma_f16(c0[0], c0[1], c0[2], c0[3],
                            ah[tm][0], ah[tm][1], ah[tm][2], ah[tm][3], b0, b1);
                    mma_f16(c1[0], c1[1], c1[2], c1[3],
                            ah[tm][0], ah[tm][1], ah[tm][2], ah[tm][3], b2, b3);
                }
            }
        }
    };

    // ---- GEMM1: A @ Wa ----
    run_gemm();
    __syncthreads();   // done reading Wa and A

    // ---- load Wb over Wa + epilogue 1: H = fp16(relu(acc + ba)) -> A buffer ----
    #pragma unroll 1
    for (int i = tid; i < 128 * 16; i += THREADS) {
        int row = i >> 4, ch = i & 15;
        uint4 v = ((const uint4*)wb)[(row << 4) + ch];
        *(uint4*)(smem + SMEM_W + row * PB + ch * 16) = v;
    }
    {
        const float* bav = (const float*)(smem + SMEM_BA);
        #pragma unroll
        for (int tm = 0; tm < 2; tm++) {
            #pragma unroll
            for (int tn = 0; tn < 8; tn++) {
                const int col = n0 + tn * 8 + (lane & 3) * 2;
                const float b0v = bav[col], b1v = bav[col + 1];
                const int r_lo = m0 + tm * 16 + (lane >> 2);
                float v0 = fmaxf(acc[tm][tn][0] + b0v, 0.f);
                float v1 = fmaxf(acc[tm][tn][1] + b1v, 0.f);
                float v2 = fmaxf(acc[tm][tn][2] + b0v, 0.f);
                float v3 = fmaxf(acc[tm][tn][3] + b1v, 0.f);
                *(uint32_t*)(smem + SMEM_A + r_lo * PB + col * 2)       = pack2h(v0, v1);
                *(uint32_t*)(smem + SMEM_A + (r_lo + 8) * PB + col * 2) = pack2h(v2, v3);
            }
        }
    }
    __syncthreads();

    // ---- GEMM2: H @ Wb ----
    run_gemm();

    // ---- epilogue 2 ----
    {
        const float* bbv = (const float*)(smem + SMEM_BB);
        #pragma unroll
        for (int tm = 0; tm < 2; tm++) {
            #pragma unroll
            for (int tn = 0; tn < 8; tn++) {
                const int col = n0 + tn * 8 + (lane & 3) * 2;
                const float b0v = bbv[col], b1v = bbv[col + 1];
                const int r_lo = row0 + m0 + tm * 16 + (lane >> 2);
                float v0 = acc[tm][tn][0] + b0v;
                float v1 = acc[tm][tn][1] + b1v;
                float v2 = acc[tm][tn][2] + b0v;
                float v3 = acc[tm][tn][3] + b1v;
                if (relu_out) {
                    v0 = fmaxf(v0, 0.f); v1 = fmaxf(v1, 0.f);
                    v2 = fmaxf(v2, 0.f); v3 = fmaxf(v3, 0.f);
                }
                if (OUT_HALF) {
                    __half* out = (__half*)outp;
                    if (r_lo < NNODES)
                        *(uint32_t*)(out + (size_t)r_lo * D + col) = pack2h(v0, v1);
                    if (r_lo + 8 < NNODES)
                        *(uint32_t*)(out + (size_t)(r_lo + 8) * D + col) = pack2h(v2, v3);
                } else {
                    float* out = (float*)outp;
                    if (r_lo < NNODES)
                        *(float2*)(out + (size_t)r_lo * D + col) = make_float2(v0, v1);
                    if (r_lo + 8 < NNODES)
                        *(float2*)(out + (size_t)(r_lo + 8) * D + col) = make_float2(v2, v3);
                }
            }
        }
    }
}

// ---------------------------------------------------------------------------
// launch
// ---------------------------------------------------------------------------
extern "C" void kernel_launch(void* const* d_in, const int* in_sizes, int n_in,
                              void* d_out, int out_size) {
    const float* inputs = (const float*)d_in[0];
    const int*   src    = (const int*)  d_in[1];
    const int*   dst    = (const int*)  d_in[2];
    const float* W1a    = (const float*)d_in[3];
    const float* b1a    = (const float*)d_in[4];
    const float* W1b    = (const float*)d_in[5];
    const float* b1b    = (const float*)d_in[6];
    const float* W2a    = (const float*)d_in[7];
    const float* b2a    = (const float*)d_in[8];
    const float* W2b    = (const float*)d_in[9];
    const float* b2b    = (const float*)d_in[10];

    __half *ginh = nullptr, *gxh = nullptr, *ghh = nullptr, *gw = nullptr;
    cudaGetSymbolAddress((void**)&ginh, g_inh);
    cudaGetSymbolAddress((void**)&gxh, g_xh);
    cudaGetSymbolAddress((void**)&ghh, g_hh);
    cudaGetSymbolAddress((void**)&gw, g_w);

    cudaFuncSetAttribute(k_mlp_hmma<1>, cudaFuncAttributeMaxDynamicSharedMemorySize, SMEM_TOTAL);
    cudaFuncSetAttribute(k_mlp_hmma<0>, cudaFuncAttributeMaxDynamicSharedMemorySize, SMEM_TOTAL);

    const int edge_blocks = (NEDGES + THREADS - 1) / THREADS;
    const int gath_blocks = (NNODES * 32 + THREADS - 1) / THREADS;
    const int mlp_blocks  = (NNODES + 127) / 128;

    k_hist_cvt<<<edge_blocks, THREADS>>>(dst, inputs);            // 0
    k_scanA_wsplit<<<256, 256>>>(W1a, W1b, W2a, W2b);             // 1
    k_scanBC<<<SCAN_BLOCKS, 256>>>();                             // 2
    k_fill<<<edge_blocks, THREADS>>>(src, dst);                   // 3  <- profiled

    // layer 1
    k_gather_h<<<gath_blocks, THREADS>>>(ginh, gxh);              // 4
    k_mlp_hmma<1><<<mlp_blocks, THREADS, SMEM_TOTAL>>>(           // 5
        gxh, gw + 0 * D * D, gw + 1 * D * D, b1a, b1b, ghh, 1);

    // layer 2
    k_gather_h<<<gath_blocks, THREADS>>>(ghh, gxh);               // 6
    k_mlp_hmma<0><<<mlp_blocks, THREADS, SMEM_TOTAL>>>(           // 7
        gxh, gw + 2 * D * D, gw + 3 * D * D, b2a, b2b, d_out, 0);
}

// round 12
// speedup vs baseline: 2.3783x; 1.0323x over previous
#include <cuda_runtime.h>
#include <cuda_fp16.h>
#include <cstdint>

#define D 128
#define NNODES 50000
#define NEDGES 600000
#define THREADS 256
#define SCAN_BLOCKS ((NNODES + 255) / 256)   // 196

// ---------------------------------------------------------------------------
// Device-global scratch (allocation-free rule)
// ---------------------------------------------------------------------------
__device__ __half g_inh[(size_t)NNODES * D];  // fp16 copy of inputs
__device__ __half g_xh[(size_t)NNODES * D];   // gathered features (fp16)
__device__ __half g_hh[(size_t)NNODES * D];   // layer-1 output (fp16)
__device__ int   g_deg[NNODES];
__device__ int   g_off[NNODES + 1];
__device__ int   g_cursor[NNODES];
__device__ int   g_adj[NEDGES];
__device__ int   g_bsum[256];
// fp16 weights, K-major [n][k], 4 matrices: W1a, W1b, W2a, W2b
__device__ __half g_w[4 * D * D];

// ---------------------------------------------------------------------------
// helpers
// ---------------------------------------------------------------------------
__device__ __forceinline__ uint32_t smem_u32(const void* p) {
    uint32_t a;
    asm("{ .reg .u64 t; cvta.to.shared.u64 t, %1; cvt.u32.u64 %0, t; }" : "=r"(a) : "l"(p));
    return a;
}

__device__ __forceinline__ void ldsm_x4(uint32_t& r0, uint32_t& r1, uint32_t& r2, uint32_t& r3,
                                        uint32_t addr) {
    asm volatile("ldmatrix.sync.aligned.m8n8.x4.shared.b16 {%0,%1,%2,%3}, [%4];"
                 : "=r"(r0), "=r"(r1), "=r"(r2), "=r"(r3) : "r"(addr));
}

__device__ __forceinline__ void mma_f16(float& c0, float& c1, float& c2, float& c3,
                                        uint32_t a0, uint32_t a1, uint32_t a2, uint32_t a3,
                                        uint32_t b0, uint32_t b1) {
    asm volatile("mma.sync.aligned.m16n8k16.row.col.f32.f16.f16.f32 "
                 "{%0,%1,%2,%3}, {%4,%5,%6,%7}, {%8,%9}, {%0,%1,%2,%3};"
                 : "+f"(c0), "+f"(c1), "+f"(c2), "+f"(c3)
                 : "r"(a0), "r"(a1), "r"(a2), "r"(a3), "r"(b0), "r"(b1));
}

__device__ __forceinline__ uint32_t pack2h(float v0, float v1) {
    __half2 h = __floats2half2_rn(v0, v1);
    return *(uint32_t*)&h;
}

__device__ __forceinline__ float2 h2f(uint32_t u) {
    __half2 h = *(__half2*)&u;
    return __half22float2(h);
}

// ---------------------------------------------------------------------------
// 0: histogram (2 edges/thread) + fused fp32->fp16 input conversion
// ---------------------------------------------------------------------------
__global__ void k_hist_cvt(const int* __restrict__ dst, const float* __restrict__ inputs) {
    int gid = blockIdx.x * blockDim.x + threadIdx.x;
    if (gid < NEDGES / 2) {
        int2 d2 = ((const int2*)dst)[gid];
        atomicAdd(&g_deg[d2.x], 1);
        atomicAdd(&g_deg[d2.y], 1);
    }
    // convert inputs: NNODES*D/8 = 800K groups of 8 floats -> uint4 (8 halves)
    const int total = NNODES * D / 8;
    const int stride = gridDim.x * blockDim.x;
    for (int i = gid; i < total; i += stride) {
        float4 a = ((const float4*)inputs)[i * 2];
        float4 b = ((const float4*)inputs)[i * 2 + 1];
        uint4 o;
        o.x = pack2h(a.x, a.y);
        o.y = pack2h(a.z, a.w);
        o.z = pack2h(b.x, b.y);
        o.w = pack2h(b.z, b.w);
        ((uint4*)g_inh)[i] = o;
    }
}

// ---------------------------------------------------------------------------
// 1: scan phase A (per-256-chunk exclusive scan) + fused weight convert
// ---------------------------------------------------------------------------
__global__ __launch_bounds__(256)
void k_scanA_wsplit(const float* __restrict__ W0, const float* __restrict__ W1,
                    const float* __restrict__ W2, const float* __restrict__ W3) {
    __shared__ int wsum[8];
    const int b = blockIdx.x, tid = threadIdx.x, lane = tid & 31, wd = tid >> 5;

    if (b < SCAN_BLOCKS) {
        int i = b * 256 + tid;
        int v = (i < NNODES) ? g_deg[i] : 0;
        if (i < NNODES) g_deg[i] = 0;            // re-zero for next call
        int s = v;
        #pragma unroll
        for (int o = 1; o < 32; o <<= 1) {
            int t = __shfl_up_sync(0xFFFFFFFFu, s, o);
            if (lane >= o) s += t;
        }
        if (lane == 31) wsum[wd] = s;
        __syncthreads();
        if (wd == 0) {
            int x = (lane < 8) ? wsum[lane] : 0;
            #pragma unroll
            for (int o = 1; o < 8; o <<= 1) {
                int t = __shfl_up_sync(0xFFFFFFFFu, x, o);
                if (lane >= o) x += t;
            }
            if (lane < 8) wsum[lane] = x;
        }
        __syncthreads();
        int excl = (wd ? wsum[wd - 1] : 0) + s - v;
        if (i < NNODES) g_off[i] = excl;
        if (tid == 255) g_bsum[b] = wsum[7];
    }

    // fused weight transpose + fp16 convert: 4*128*128 = 65536 = grid exactly
    {
        int gidx = b * 256 + tid;
        int mat = gidx >> 14;
        int idx = gidx & 16383;
        const float* W = (mat == 0) ? W0 : (mat == 1) ? W1 : (mat == 2) ? W2 : W3;
        int n = idx >> 7, k = idx & 127;
        g_w[gidx] = __float2half_rn(W[k * D + n]);
    }
}

// ---------------------------------------------------------------------------
// 2: scan phase BC
// ---------------------------------------------------------------------------
__global__ __launch_bounds__(256)
void k_scanBC() {
    __shared__ int pre_s;
    __shared__ int wred[8];
    const int b = blockIdx.x, tid = threadIdx.x, lane = tid & 31, wd = tid >> 5;

    int s = 0;
    for (int j = tid; j < b; j += 256) s += g_bsum[j];
    #pragma unroll
    for (int o = 16; o > 0; o >>= 1) s += __shfl_down_sync(0xFFFFFFFFu, s, o);
    if (lane == 0) wred[wd] = s;
    __syncthreads();
    if (tid == 0) {
        int t = 0;
        #pragma unroll
        for (int w = 0; w < 8; w++) t += wred[w];
        pre_s = t;
    }
    __syncthreads();

    int i = b * 256 + tid;
    if (i < NNODES) {
        int off = g_off[i] + pre_s;
        g_off[i] = off;
        g_cursor[i] = off;
    }
    if (b == 0 && tid == 0) g_off[NNODES] = NEDGES;
}

// ---------------------------------------------------------------------------
// 3: fill CSR adjacency (2 edges/thread)
// ---------------------------------------------------------------------------
__global__ void k_fill(const int* __restrict__ src, const int* __restrict__ dst) {
    int gid = blockIdx.x * blockDim.x + threadIdx.x;
    if (gid < NEDGES / 2) {
        int2 s2 = ((const int2*)src)[gid];
        int2 d2 = ((const int2*)dst)[gid];
        int p0 = atomicAdd(&g_cursor[d2.x], 1);
        g_adj[p0] = s2.x;
        int p1 = atomicAdd(&g_cursor[d2.y], 1);
        g_adj[p1] = s2.y;
    }
}

// ---------------------------------------------------------------------------
// gather (fp16, half-warp per node): x[i] = h[i] + sum_{s in adj(i)} h[s]
// 16 lanes x uint4 (16B) = 256B row. fp32 accumulation.
// ---------------------------------------------------------------------------
__global__ __launch_bounds__(THREADS)
void k_gather_h(const __half* __restrict__ h, __half* __restrict__ x) {
    int gwarp = (blockIdx.x * blockDim.x + threadIdx.x) >> 5;
    int lane = threadIdx.x & 31;
    int node = gwarp * 2 + (lane >> 4);
    int l16  = lane & 15;
    if (node >= NNODES) return;
    const uint4* hp = (const uint4*)h;   // 16 uint4 per row

    uint4 self = hp[(size_t)node * 16 + l16];
    float acc[8];
    {
        float2 f;
        f = h2f(self.x); acc[0] = f.x; acc[1] = f.y;
        f = h2f(self.y); acc[2] = f.x; acc[3] = f.y;
        f = h2f(self.z); acc[4] = f.x; acc[5] = f.y;
        f = h2f(self.w); acc[6] = f.x; acc[7] = f.y;
    }

    int beg = g_off[node], end = g_off[node + 1];
    int p = beg;
    for (; p + 4 <= end; p += 4) {
        int s0 = g_adj[p], s1 = g_adj[p + 1], s2 = g_adj[p + 2], s3 = g_adj[p + 3];
        uint4 v0 = hp[(size_t)s0 * 16 + l16];
        uint4 v1 = hp[(size_t)s1 * 16 + l16];
        uint4 v2 = hp[(size_t)s2 * 16 + l16];
        uint4 v3 = hp[(size_t)s3 * 16 + l16];
        float2 f;
        f = h2f(v0.x); acc[0] += f.x; acc[1] += f.y;
        f = h2f(v0.y); acc[2] += f.x; acc[3] += f.y;
        f = h2f(v0.z); acc[4] += f.x; acc[5] += f.y;
        f = h2f(v0.w); acc[6] += f.x; acc[7] += f.y;
        f = h2f(v1.x); acc[0] += f.x; acc[1] += f.y;
        f = h2f(v1.y); acc[2] += f.x; acc[3] += f.y;
        f = h2f(v1.z); acc[4] += f.x; acc[5] += f.y;
        f = h2f(v1.w); acc[6] += f.x; acc[7] += f.y;
        f = h2f(v2.x); acc[0] += f.x; acc[1] += f.y;
        f = h2f(v2.y); acc[2] += f.x; acc[3] += f.y;
        f = h2f(v2.z); acc[4] += f.x; acc[5] += f.y;
        f = h2f(v2.w); acc[6] += f.x; acc[7] += f.y;
        f = h2f(v3.x); acc[0] += f.x; acc[1] += f.y;
        f = h2f(v3.y); acc[2] += f.x; acc[3] += f.y;
        f = h2f(v3.z); acc[4] += f.x; acc[5] += f.y;
        f = h2f(v3.w); acc[6] += f.x; acc[7] += f.y;
    }
    for (; p < end; ++p) {
        int s = g_adj[p];
        uint4 v = hp[(size_t)s * 16 + l16];
        float2 f;
        f = h2f(v.x); acc[0] += f.x; acc[1] += f.y;
        f = h2f(v.y); acc[2] += f.x; acc[3] += f.y;
        f = h2f(v.z); acc[4] += f.x; acc[5] += f.y;
        f = h2f(v.w); acc[6] += f.x; acc[7] += f.y;
    }
    uint4 o;
    o.x = pack2h(acc[0], acc[1]);
    o.y = pack2h(acc[2], acc[3]);
    o.z = pack2h(acc[4], acc[5]);
    o.w = pack2h(acc[6], acc[7]);
    ((uint4*)x)[(size_t)node * 16 + l16] = o;
}

// ---------------------------------------------------------------------------
// HMMA fused MLP (pure fp16, staged weights): 3 CTAs/SM.
// Wa -> GEMM1 -> (epi1 + load Wb over Wa) -> GEMM2.
// 8 warps, 4(m)x2(n) warp grid, warp tile 32x64.
// ---------------------------------------------------------------------------
#define PB 272
#define SMEM_BA   0
#define SMEM_BB   512
#define SMEM_A    1024
#define ABUF_SZ   (128 * PB)                  // 34816
#define SMEM_W    (SMEM_A + ABUF_SZ)          // ONE weight matrix at a time
#define SMEM_TOTAL (SMEM_W + ABUF_SZ)         // 70656 B -> 3 CTAs/SM

template <int OUT_HALF>
__global__ __launch_bounds__(THREADS, 3)
void k_mlp_hmma(const __half* __restrict__ x,
                const __half* __restrict__ wa, const __half* __restrict__ wb,
                const float* __restrict__ ba, const float* __restrict__ bb,
                void* __restrict__ outp, int relu_out) {
    extern __shared__ char smem[];
    const uint32_t sb = smem_u32(smem);
    const int tid = threadIdx.x, wid = tid >> 5, lane = tid & 31;
    const int row0 = blockIdx.x * 128;

    // ---- biases ----
    if (tid < 128) {
        ((float*)(smem + SMEM_BA))[tid] = ba[tid];
        ((float*)(smem + SMEM_BB))[tid] = bb[tid];
    }

    // ---- Wa -> padded smem (2048 x 16B chunks); rolled to cap reg pressure ----
    #pragma unroll 1
    for (int i = tid; i < 128 * 16; i += THREADS) {
        int row = i >> 4, ch = i & 15;
        uint4 v = ((const uint4*)wa)[(row << 4) + ch];
        *(uint4*)(smem + SMEM_W + row * PB + ch * 16) = v;
    }

    // ---- A tile: straight fp16 copy (128 rows x 256B) ----
    {
        int r  = tid >> 1;
        int c0 = (tid & 1) * 128;
        int grow = row0 + r;
        char* ap = smem + SMEM_A + r * PB + c0;
        if (grow < NNODES) {
            const char* xp = (const char*)(x + (size_t)grow * D) + c0;
            #pragma unroll
            for (int c = 0; c < 128; c += 16)
                *(uint4*)(ap + c) = *(const uint4*)(xp + c);
        } else {
            #pragma unroll
            for (int c = 0; c < 128; c += 16)
                *(uint4*)(ap + c) = make_uint4(0u, 0u, 0u, 0u);
        }
    }
    __syncthreads();

    const int warp_m = wid & 3;
    const int warp_n = wid >> 2;
    const int m0 = warp_m * 32;
    const int n0 = warp_n * 64;

    const uint32_t a_off = (uint32_t)((m0 + (lane & 15)) * PB + (lane >> 4) * 16);
    const uint32_t b_off = (uint32_t)((n0 + ((lane >> 4) << 3) + (lane & 7)) * PB
                                      + ((lane >> 3) & 1) * 16);

    const uint32_t Abuf = sb + SMEM_A;
    const uint32_t Wbuf = sb + SMEM_W;

    float acc[2][8][4];

    auto run_gemm = [&]() {
        #pragma unroll
        for (int tm = 0; tm < 2; tm++)
            #pragma unroll
            for (int tn = 0; tn < 8; tn++)
                #pragma unroll
                for (int q = 0; q < 4; q++) acc[tm][tn][q] = 0.f;

        #pragma unroll
        for (int s = 0; s < 8; s++) {
            const uint32_t kb = s * 32;
            uint32_t ah[2][4];
            ldsm_x4(ah[0][0], ah[0][1], ah[0][2], ah[0][3], Abuf + a_off + kb);
            ldsm_x4(ah[1][0], ah[1][1], ah[1][2], ah[1][3], Abuf + a_off + 16 * PB + kb);

            #pragma unroll
            for (int p = 0; p < 4; p++) {
                uint32_t b0, b1, b2, b3;
                ldsm_x4(b0, b1, b2, b3, Wbuf + b_off + p * 16 * PB + kb);
                #pragma unroll
                for (int tm = 0; tm < 2; tm++) {
                    float* c0 = acc[tm][p * 2];
                    float* c1 = acc[tm][p * 2 + 1];
                    mma_f16(c0[0], c0[1], c0[2], c0[3],
                            ah[tm][0], ah[tm][1], ah[tm][2], ah[tm][3], b0, b1);
                    mma_f16(c1[0], c1[1], c1[2], c1[3],
                            ah[tm][0], ah[tm][1], ah[tm][2], ah[tm][3], b2, b3);
                }
            }
        }
    };

    // ---- GEMM1: A @ Wa ----
    run_gemm();
    __syncthreads();

    // ---- load Wb over Wa + epilogue 1: H = fp16(relu(acc + ba)) -> A buffer ----
    #pragma unroll 1
    for (int i = tid; i < 128 * 16; i += THREADS) {
        int row = i >> 4, ch = i & 15;
        uint4 v = ((const uint4*)wb)[(row << 4) + ch];
        *(uint4*)(smem + SMEM_W + row * PB + ch * 16) = v;
    }
    {
        const float* bav = (const float*)(smem + SMEM_BA);
        #pragma unroll
        for (int tm = 0; tm < 2; tm++) {
            #pragma unroll
            for (int tn = 0; tn < 8; tn++) {
                const int col = n0 + tn * 8 + (lane & 3) * 2;
                const float b0v = bav[col], b1v = bav[col + 1];
                const int r_lo = m0 + tm * 16 + (lane >> 2);
                float v0 = fmaxf(acc[tm][tn][0] + b0v, 0.f);
                float v1 = fmaxf(acc[tm][tn][1] + b1v, 0.f);
                float v2 = fmaxf(acc[tm][tn][2] + b0v, 0.f);
                float v3 = fmaxf(acc[tm][tn][3] + b1v, 0.f);
                *(uint32_t*)(smem + SMEM_A + r_lo * PB + col * 2)       = pack2h(v0, v1);
                *(uint32_t*)(smem + SMEM_A + (r_lo + 8) * PB + col * 2) = pack2h(v2, v3);
            }
        }
    }
    __syncthreads();

    // ---- GEMM2: H @ Wb ----
    run_gemm();

    // ---- epilogue 2 ----
    {
        const float* bbv = (const float*)(smem + SMEM_BB);
        #pragma unroll
        for (int tm = 0; tm < 2; tm++) {
            #pragma unroll
            for (int tn = 0; tn < 8; tn++) {
                const int col = n0 + tn * 8 + (lane & 3) * 2;
                const float b0v = bbv[col], b1v = bbv[col + 1];
                const int r_lo = row0 + m0 + tm * 16 + (lane >> 2);
                float v0 = acc[tm][tn][0] + b0v;
                float v1 = acc[tm][tn][1] + b1v;
                float v2 = acc[tm][tn][2] + b0v;
                float v3 = acc[tm][tn][3] + b1v;
                if (relu_out) {
                    v0 = fmaxf(v0, 0.f); v1 = fmaxf(v1, 0.f);
                    v2 = fmaxf(v2, 0.f); v3 = fmaxf(v3, 0.f);
                }
                if (OUT_HALF) {
                    __half* out = (__half*)outp;
                    if (r_lo < NNODES)
                        *(uint32_t*)(out + (size_t)r_lo * D + col) = pack2h(v0, v1);
                    if (r_lo + 8 < NNODES)
                        *(uint32_t*)(out + (size_t)(r_lo + 8) * D + col) = pack2h(v2, v3);
                } else {
                    float* out = (float*)outp;
                    if (r_lo < NNODES)
                        *(float2*)(out + (size_t)r_lo * D + col) = make_float2(v0, v1);
                    if (r_lo + 8 < NNODES)
                        *(float2*)(out + (size_t)(r_lo + 8) * D + col) = make_float2(v2, v3);
                }
            }
        }
    }
}

// ---------------------------------------------------------------------------
// launch
// ---------------------------------------------------------------------------
extern "C" void kernel_launch(void* const* d_in, const int* in_sizes, int n_in,
                              void* d_out, int out_size) {
    const float* inputs = (const float*)d_in[0];
    const int*   src    = (const int*)  d_in[1];
    const int*   dst    = (const int*)  d_in[2];
    const float* W1a    = (const float*)d_in[3];
    const float* b1a    = (const float*)d_in[4];
    const float* W1b    = (const float*)d_in[5];
    const float* b1b    = (const float*)d_in[6];
    const float* W2a    = (const float*)d_in[7];
    const float* b2a    = (const float*)d_in[8];
    const float* W2b    = (const float*)d_in[9];
    const float* b2b    = (const float*)d_in[10];

    __half *ginh = nullptr, *gxh = nullptr, *ghh = nullptr, *gw = nullptr;
    cudaGetSymbolAddress((void**)&ginh, g_inh);
    cudaGetSymbolAddress((void**)&gxh, g_xh);
    cudaGetSymbolAddress((void**)&ghh, g_hh);
    cudaGetSymbolAddress((void**)&gw, g_w);

    cudaFuncSetAttribute(k_mlp_hmma<1>, cudaFuncAttributeMaxDynamicSharedMemorySize, SMEM_TOTAL);
    cudaFuncSetAttribute(k_mlp_hmma<0>, cudaFuncAttributeMaxDynamicSharedMemorySize, SMEM_TOTAL);

    const int edge2_blocks = (NEDGES / 2 + THREADS - 1) / THREADS;   // 1172
    const int gath_blocks  = (((NNODES + 1) / 2) * 32 + THREADS - 1) / THREADS; // 3125
    const int mlp_blocks   = (NNODES + 127) / 128;

    k_hist_cvt<<<edge2_blocks, THREADS>>>(dst, inputs);           // 0
    k_scanA_wsplit<<<256, 256>>>(W1a, W1b, W2a, W2b);             // 1
    k_scanBC<<<SCAN_BLOCKS, 256>>>();                             // 2
    k_fill<<<edge2_blocks, THREADS>>>(src, dst);                  // 3  <- profiled

    // layer 1
    k_gather_h<<<gath_blocks, THREADS>>>(ginh, gxh);              // 4
    k_mlp_hmma<1><<<mlp_blocks, THREADS, SMEM_TOTAL>>>(           // 5
        gxh, gw + 0 * D * D, gw + 1 * D * D, b1a, b1b, ghh, 1);

    // layer 2
    k_gather_h<<<gath_blocks, THREADS>>>(ghh, gxh);               // 6
    k_mlp_hmma<0><<<mlp_blocks, THREADS, SMEM_TOTAL>>>(           // 7
        gxh, gw + 2 * D * D, gw + 3 * D * D, b2a, b2b, d_out, 0);
}

// round 13
// speedup vs baseline: 2.3831x; 1.0020x over previous
#include <cuda_runtime.h>
#include <cuda_fp16.h>
#include <cstdint>

#define D 128
#define NNODES 50000
#define NEDGES 600000
#define THREADS 256
#define SCAN_BLOCKS ((NNODES + 255) / 256)   // 196

// ---------------------------------------------------------------------------
// Device-global scratch (allocation-free rule)
// ---------------------------------------------------------------------------
__device__ __half g_inh[(size_t)NNODES * D];  // fp16 copy of inputs
__device__ __half g_xh[(size_t)NNODES * D];   // gathered features (fp16)
__device__ __half g_hh[(size_t)NNODES * D];   // layer-1 output (fp16)
__device__ int   g_deg[NNODES];
__device__ int   g_off[NNODES + 1];
__device__ int   g_seq[NEDGES];               // per-edge within-node sequence #
__device__ int   g_adj[NEDGES];
__device__ int   g_bsum[256];
// fp16 weights, K-major [n][k], 4 matrices: W1a, W1b, W2a, W2b
__device__ __half g_w[4 * D * D];

// ---------------------------------------------------------------------------
// helpers
// ---------------------------------------------------------------------------
__device__ __forceinline__ uint32_t smem_u32(const void* p) {
    uint32_t a;
    asm("{ .reg .u64 t; cvta.to.shared.u64 t, %1; cvt.u32.u64 %0, t; }" : "=r"(a) : "l"(p));
    return a;
}

__device__ __forceinline__ void ldsm_x4(uint32_t& r0, uint32_t& r1, uint32_t& r2, uint32_t& r3,
                                        uint32_t addr) {
    asm volatile("ldmatrix.sync.aligned.m8n8.x4.shared.b16 {%0,%1,%2,%3}, [%4];"
                 : "=r"(r0), "=r"(r1), "=r"(r2), "=r"(r3) : "r"(addr));
}

__device__ __forceinline__ void mma_f16(float& c0, float& c1, float& c2, float& c3,
                                        uint32_t a0, uint32_t a1, uint32_t a2, uint32_t a3,
                                        uint32_t b0, uint32_t b1) {
    asm volatile("mma.sync.aligned.m16n8k16.row.col.f32.f16.f16.f32 "
                 "{%0,%1,%2,%3}, {%4,%5,%6,%7}, {%8,%9}, {%0,%1,%2,%3};"
                 : "+f"(c0), "+f"(c1), "+f"(c2), "+f"(c3)
                 : "r"(a0), "r"(a1), "r"(a2), "r"(a3), "r"(b0), "r"(b1));
}

__device__ __forceinline__ uint32_t pack2h(float v0, float v1) {
    __half2 h = __floats2half2_rn(v0, v1);
    return *(uint32_t*)&h;
}

__device__ __forceinline__ float2 h2f(uint32_t u) {
    __half2 h = *(__half2*)&u;
    return __half22float2(h);
}

// ---------------------------------------------------------------------------
// 0: histogram (stores per-edge seq) + fused fp32->fp16 input conversion
// ---------------------------------------------------------------------------
__global__ void k_hist_cvt(const int* __restrict__ dst, const float* __restrict__ inputs) {
    int gid = blockIdx.x * blockDim.x + threadIdx.x;
    if (gid < NEDGES / 2) {
        int2 d2 = ((const int2*)dst)[gid];
        int s0 = atomicAdd(&g_deg[d2.x], 1);
        int s1 = atomicAdd(&g_deg[d2.y], 1);
        ((int2*)g_seq)[gid] = make_int2(s0, s1);
    }
    // convert inputs: NNODES*D/8 = 800K groups of 8 floats -> uint4 (8 halves)
    const int total = NNODES * D / 8;
    const int stride = gridDim.x * blockDim.x;
    for (int i = gid; i < total; i += stride) {
        float4 a = ((const float4*)inputs)[i * 2];
        float4 b = ((const float4*)inputs)[i * 2 + 1];
        uint4 o;
        o.x = pack2h(a.x, a.y);
        o.y = pack2h(a.z, a.w);
        o.z = pack2h(b.x, b.y);
        o.w = pack2h(b.z, b.w);
        ((uint4*)g_inh)[i] = o;
    }
}

// ---------------------------------------------------------------------------
// 1: scan phase A (per-256-chunk exclusive scan) + fused weight convert
// ---------------------------------------------------------------------------
__global__ __launch_bounds__(256)
void k_scanA_wsplit(const float* __restrict__ W0, const float* __restrict__ W1,
                    const float* __restrict__ W2, const float* __restrict__ W3) {
    __shared__ int wsum[8];
    const int b = blockIdx.x, tid = threadIdx.x, lane = tid & 31, wd = tid >> 5;

    if (b < SCAN_BLOCKS) {
        int i = b * 256 + tid;
        int v = (i < NNODES) ? g_deg[i] : 0;
        if (i < NNODES) g_deg[i] = 0;            // re-zero for next call
        int s = v;
        #pragma unroll
        for (int o = 1; o < 32; o <<= 1) {
            int t = __shfl_up_sync(0xFFFFFFFFu, s, o);
            if (lane >= o) s += t;
        }
        if (lane == 31) wsum[wd] = s;
        __syncthreads();
        if (wd == 0) {
            int x = (lane < 8) ? wsum[lane] : 0;
            #pragma unroll
            for (int o = 1; o < 8; o <<= 1) {
                int t = __shfl_up_sync(0xFFFFFFFFu, x, o);
                if (lane >= o) x += t;
            }
            if (lane < 8) wsum[lane] = x;
        }
        __syncthreads();
        int excl = (wd ? wsum[wd - 1] : 0) + s - v;
        if (i < NNODES) g_off[i] = excl;
        if (tid == 255) g_bsum[b] = wsum[7];
    }

    // fused weight transpose + fp16 convert: 4*128*128 = 65536 = grid exactly
    {
        int gidx = b * 256 + tid;
        int mat = gidx >> 14;
        int idx = gidx & 16383;
        const float* W = (mat == 0) ? W0 : (mat == 1) ? W1 : (mat == 2) ? W2 : W3;
        int n = idx >> 7, k = idx & 127;
        g_w[gidx] = __float2half_rn(W[k * D + n]);
    }
}

// ---------------------------------------------------------------------------
// 2: scan phase BC (finalize offsets; no cursor needed anymore)
// ---------------------------------------------------------------------------
__global__ __launch_bounds__(256)
void k_scanBC() {
    __shared__ int pre_s;
    __shared__ int wred[8];
    const int b = blockIdx.x, tid = threadIdx.x, lane = tid & 31, wd = tid >> 5;

    int s = 0;
    for (int j = tid; j < b; j += 256) s += g_bsum[j];
    #pragma unroll
    for (int o = 16; o > 0; o >>= 1) s += __shfl_down_sync(0xFFFFFFFFu, s, o);
    if (lane == 0) wred[wd] = s;
    __syncthreads();
    if (tid == 0) {
        int t = 0;
        #pragma unroll
        for (int w = 0; w < 8; w++) t += wred[w];
        pre_s = t;
    }
    __syncthreads();

    int i = b * 256 + tid;
    if (i < NNODES) g_off[i] += pre_s;
    if (b == 0 && tid == 0) g_off[NNODES] = NEDGES;
}

// ---------------------------------------------------------------------------
// 3: fill CSR adjacency — ATOMIC-FREE: pos = off[dst] + seq
// ---------------------------------------------------------------------------
__global__ void k_fill(const int* __restrict__ src, const int* __restrict__ dst) {
    int gid = blockIdx.x * blockDim.x + threadIdx.x;
    if (gid < NEDGES / 2) {
        int2 s2 = ((const int2*)src)[gid];
        int2 d2 = ((const int2*)dst)[gid];
        int2 q2 = ((const int2*)g_seq)[gid];
        int p0 = g_off[d2.x] + q2.x;
        int p1 = g_off[d2.y] + q2.y;
        g_adj[p0] = s2.x;
        g_adj[p1] = s2.y;
    }
}

// ---------------------------------------------------------------------------
// gather (fp16, half-warp per node): x[i] = h[i] + sum_{s in adj(i)} h[s]
// 16 lanes x uint4 (16B) = 256B row. fp32 accumulation.
// ---------------------------------------------------------------------------
__global__ __launch_bounds__(THREADS)
void k_gather_h(const __half* __restrict__ h, __half* __restrict__ x) {
    int gwarp = (blockIdx.x * blockDim.x + threadIdx.x) >> 5;
    int lane = threadIdx.x & 31;
    int node = gwarp * 2 + (lane >> 4);
    int l16  = lane & 15;
    if (node >= NNODES) return;
    const uint4* hp = (const uint4*)h;   // 16 uint4 per row

    uint4 self = hp[(size_t)node * 16 + l16];
    float acc[8];
    {
        float2 f;
        f = h2f(self.x); acc[0] = f.x; acc[1] = f.y;
        f = h2f(self.y); acc[2] = f.x; acc[3] = f.y;
        f = h2f(self.z); acc[4] = f.x; acc[5] = f.y;
        f = h2f(self.w); acc[6] = f.x; acc[7] = f.y;
    }

    int beg = g_off[node], end = g_off[node + 1];
    int p = beg;
    for (; p + 4 <= end; p += 4) {
        int s0 = g_adj[p], s1 = g_adj[p + 1], s2 = g_adj[p + 2], s3 = g_adj[p + 3];
        uint4 v0 = hp[(size_t)s0 * 16 + l16];
        uint4 v1 = hp[(size_t)s1 * 16 + l16];
        uint4 v2 = hp[(size_t)s2 * 16 + l16];
        uint4 v3 = hp[(size_t)s3 * 16 + l16];
        float2 f;
        f = h2f(v0.x); acc[0] += f.x; acc[1] += f.y;
        f = h2f(v0.y); acc[2] += f.x; acc[3] += f.y;
        f = h2f(v0.z); acc[4] += f.x; acc[5] += f.y;
        f = h2f(v0.w); acc[6] += f.x; acc[7] += f.y;
        f = h2f(v1.x); acc[0] += f.x; acc[1] += f.y;
        f = h2f(v1.y); acc[2] += f.x; acc[3] += f.y;
        f = h2f(v1.z); acc[4] += f.x; acc[5] += f.y;
        f = h2f(v1.w); acc[6] += f.x; acc[7] += f.y;
        f = h2f(v2.x); acc[0] += f.x; acc[1] += f.y;
        f = h2f(v2.y); acc[2] += f.x; acc[3] += f.y;
        f = h2f(v2.z); acc[4] += f.x; acc[5] += f.y;
        f = h2f(v2.w); acc[6] += f.x; acc[7] += f.y;
        f = h2f(v3.x); acc[0] += f.x; acc[1] += f.y;
        f = h2f(v3.y); acc[2] += f.x; acc[3] += f.y;
        f = h2f(v3.z); acc[4] += f.x; acc[5] += f.y;
        f = h2f(v3.w); acc[6] += f.x; acc[7] += f.y;
    }
    for (; p < end; ++p) {
        int s = g_adj[p];
        uint4 v = hp[(size_t)s * 16 + l16];
        float2 f;
        f = h2f(v.x); acc[0] += f.x; acc[1] += f.y;
        f = h2f(v.y); acc[2] += f.x; acc[3] += f.y;
        f = h2f(v.z); acc[4] += f.x; acc[5] += f.y;
        f = h2f(v.w); acc[6] += f.x; acc[7] += f.y;
    }
    uint4 o;
    o.x = pack2h(acc[0], acc[1]);
    o.y = pack2h(acc[2], acc[3]);
    o.z = pack2h(acc[4], acc[5]);
    o.w = pack2h(acc[6], acc[7]);
    ((uint4*)x)[(size_t)node * 16 + l16] = o;
}

// ---------------------------------------------------------------------------
// HMMA fused MLP (pure fp16, staged weights): 3 CTAs/SM.
// Wa -> GEMM1 -> (epi1 + load Wb over Wa) -> GEMM2.
// 8 warps, 4(m)x2(n) warp grid, warp tile 32x64.
// ---------------------------------------------------------------------------
#define PB 272
#define SMEM_BA   0
#define SMEM_BB   512
#define SMEM_A    1024
#define ABUF_SZ   (128 * PB)                  // 34816
#define SMEM_W    (SMEM_A + ABUF_SZ)          // ONE weight matrix at a time
#define SMEM_TOTAL (SMEM_W + ABUF_SZ)         // 70656 B -> 3 CTAs/SM

template <int OUT_HALF>
__global__ __launch_bounds__(THREADS, 3)
void k_mlp_hmma(const __half* __restrict__ x,
                const __half* __restrict__ wa, const __half* __restrict__ wb,
                const float* __restrict__ ba, const float* __restrict__ bb,
                void* __restrict__ outp, int relu_out) {
    extern __shared__ char smem[];
    const uint32_t sb = smem_u32(smem);
    const int tid = threadIdx.x, wid = tid >> 5, lane = tid & 31;
    const int row0 = blockIdx.x * 128;

    // ---- biases ----
    if (tid < 128) {
        ((float*)(smem + SMEM_BA))[tid] = ba[tid];
        ((float*)(smem + SMEM_BB))[tid] = bb[tid];
    }

    // ---- Wa -> padded smem (2048 x 16B chunks); rolled to cap reg pressure ----
    #pragma unroll 1
    for (int i = tid; i < 128 * 16; i += THREADS) {
        int row = i >> 4, ch = i & 15;
        uint4 v = ((const uint4*)wa)[(row << 4) + ch];
        *(uint4*)(smem + SMEM_W + row * PB + ch * 16) = v;
    }

    // ---- A tile: straight fp16 copy (128 rows x 256B) ----
    {
        int r  = tid >> 1;
        int c0 = (tid & 1) * 128;
        int grow = row0 + r;
        char* ap = smem + SMEM_A + r * PB + c0;
        if (grow < NNODES) {
            const char* xp = (const char*)(x + (size_t)grow * D) + c0;
            #pragma unroll
            for (int c = 0; c < 128; c += 16)
                *(uint4*)(ap + c) = *(const uint4*)(xp + c);
        } else {
            #pragma unroll
            for (int c = 0; c < 128; c += 16)
                *(uint4*)(ap + c) = make_uint4(0u, 0u, 0u, 0u);
        }
    }
    __syncthreads();

    const int warp_m = wid & 3;
    const int warp_n = wid >> 2;
    const int m0 = warp_m * 32;
    const int n0 = warp_n * 64;

    const uint32_t a_off = (uint32_t)((m0 + (lane & 15)) * PB + (lane >> 4) * 16);
    const uint32_t b_off = (uint32_t)((n0 + ((lane >> 4) << 3) + (lane & 7)) * PB
                                      + ((lane >> 3) & 1) * 16);

    const uint32_t Abuf = sb + SMEM_A;
    const uint32_t Wbuf = sb + SMEM_W;

    float acc[2][8][4];

    auto run_gemm = [&]() {
        #pragma unroll
        for (int tm = 0; tm < 2; tm++)
            #pragma unroll
            for (int tn = 0; tn < 8; tn++)
                #pragma unroll
                for (int q = 0; q < 4; q++) acc[tm][tn][q] = 0.f;

        #pragma unroll
        for (int s = 0; s < 8; s++) {
            const uint32_t kb = s * 32;
            uint32_t ah[2][4];
            ldsm_x4(ah[0][0], ah[0][1], ah[0][2], ah[0][3], Abuf + a_off + kb);
            ldsm_x4(ah[1][0], ah[1][1], ah[1][2], ah[1][3], Abuf + a_off + 16 * PB + kb);

            #pragma unroll
            for (int p = 0; p < 4; p++) {
                uint32_t b0, b1, b2, b3;
                ldsm_x4(b0, b1, b2, b3, Wbuf + b_off + p * 16 * PB + kb);
                #pragma unroll
                for (int tm = 0; tm < 2; tm++) {
                    float* c0 = acc[tm][p * 2];
                    float* c1 = acc[tm][p * 2 + 1];
                    mma_f16(c0[0], c0[1], c0[2], c0[3],
                            ah[tm][0], ah[tm][1], ah[tm][2], ah[tm][3], b0, b1);
                    mma_f16(c1[0], c1[1], c1[2], c1[3],
                            ah[tm][0], ah[tm][1], ah[tm][2], ah[tm][3], b2, b3);
                }
            }
        }
    };

    // ---- GEMM1: A @ Wa ----
    run_gemm();
    __syncthreads();

    // ---- load Wb over Wa + epilogue 1: H = fp16(relu(acc + ba)) -> A buffer ----
    #pragma unroll 1
    for (int i = tid; i < 128 * 16; i += THREADS) {
        int row = i >> 4, ch = i & 15;
        uint4 v = ((const uint4*)wb)[(row << 4) + ch];
        *(uint4*)(smem + SMEM_W + row * PB + ch * 16) = v;
    }
    {
        const float* bav = (const float*)(smem + SMEM_BA);
        #pragma unroll
        for (int tm = 0; tm < 2; tm++) {
            #pragma unroll
            for (int tn = 0; tn < 8; tn++) {
                const int col = n0 + tn * 8 + (lane & 3) * 2;
                const float b0v = bav[col], b1v = bav[col + 1];
                const int r_lo = m0 + tm * 16 + (lane >> 2);
                float v0 = fmaxf(acc[tm][tn][0] + b0v, 0.f);
                float v1 = fmaxf(acc[tm][tn][1] + b1v, 0.f);
                float v2 = fmaxf(acc[tm][tn][2] + b0v, 0.f);
                float v3 = fmaxf(acc[tm][tn][3] + b1v, 0.f);
                *(uint32_t*)(smem + SMEM_A + r_lo * PB + col * 2)       = pack2h(v0, v1);
                *(uint32_t*)(smem + SMEM_A + (r_lo + 8) * PB + col * 2) = pack2h(v2, v3);
            }
        }
    }
    __syncthreads();

    // ---- GEMM2: H @ Wb ----
    run_gemm();

    // ---- epilogue 2 ----
    {
        const float* bbv = (const float*)(smem + SMEM_BB);
        #pragma unroll
        for (int tm = 0; tm < 2; tm++) {
            #pragma unroll
            for (int tn = 0; tn < 8; tn++) {
                const int col = n0 + tn * 8 + (lane & 3) * 2;
                const float b0v = bbv[col], b1v = bbv[col + 1];
                const int r_lo = row0 + m0 + tm * 16 + (lane >> 2);
                float v0 = acc[tm][tn][0] + b0v;
                float v1 = acc[tm][tn][1] + b1v;
                float v2 = acc[tm][tn][2] + b0v;
                float v3 = acc[tm][tn][3] + b1v;
                if (relu_out) {
                    v0 = fmaxf(v0, 0.f); v1 = fmaxf(v1, 0.f);
                    v2 = fmaxf(v2, 0.f); v3 = fmaxf(v3, 0.f);
                }
                if (OUT_HALF) {
                    __half* out = (__half*)outp;
                    if (r_lo < NNODES)
                        *(uint32_t*)(out + (size_t)r_lo * D + col) = pack2h(v0, v1);
                    if (r_lo + 8 < NNODES)
                        *(uint32_t*)(out + (size_t)(r_lo + 8) * D + col) = pack2h(v2, v3);
                } else {
                    float* out = (float*)outp;
                    if (r_lo < NNODES)
                        *(float2*)(out + (size_t)r_lo * D + col) = make_float2(v0, v1);
                    if (r_lo + 8 < NNODES)
                        *(float2*)(out + (size_t)(r_lo + 8) * D + col) = make_float2(v2, v3);
                }
            }
        }
    }
}

// ---------------------------------------------------------------------------
// launch
// ---------------------------------------------------------------------------
extern "C" void kernel_launch(void* const* d_in, const int* in_sizes, int n_in,
                              void* d_out, int out_size) {
    const float* inputs = (const float*)d_in[0];
    const int*   src    = (const int*)  d_in[1];
    const int*   dst    = (const int*)  d_in[2];
    const float* W1a    = (const float*)d_in[3];
    const float* b1a    = (const float*)d_in[4];
    const float* W1b    = (const float*)d_in[5];
    const float* b1b    = (const float*)d_in[6];
    const float* W2a    = (const float*)d_in[7];
    const float* b2a    = (const float*)d_in[8];
    const float* W2b    = (const float*)d_in[9];
    const float* b2b    = (const float*)d_in[10];

    __half *ginh = nullptr, *gxh = nullptr, *ghh = nullptr, *gw = nullptr;
    cudaGetSymbolAddress((void**)&ginh, g_inh);
    cudaGetSymbolAddress((void**)&gxh, g_xh);
    cudaGetSymbolAddress((void**)&ghh, g_hh);
    cudaGetSymbolAddress((void**)&gw, g_w);

    cudaFuncSetAttribute(k_mlp_hmma<1>, cudaFuncAttributeMaxDynamicSharedMemorySize, SMEM_TOTAL);
    cudaFuncSetAttribute(k_mlp_hmma<0>, cudaFuncAttributeMaxDynamicSharedMemorySize, SMEM_TOTAL);

    const int edge2_blocks = (NEDGES / 2 + THREADS - 1) / THREADS;   // 1172
    const int gath_blocks  = (((NNODES + 1) / 2) * 32 + THREADS - 1) / THREADS; // 3125
    const int mlp_blocks   = (NNODES + 127) / 128;

    k_hist_cvt<<<edge2_blocks, THREADS>>>(dst, inputs);           // 0
    k_scanA_wsplit<<<256, 256>>>(W1a, W1b, W2a, W2b);             // 1
    k_scanBC<<<SCAN_BLOCKS, 256>>>();                             // 2
    k_fill<<<edge2_blocks, THREADS>>>(src, dst);                  // 3  <- profiled

    // layer 1
    k_gather_h<<<gath_blocks, THREADS>>>(ginh, gxh);              // 4
    k_mlp_hmma<1><<<mlp_blocks, THREADS, SMEM_TOTAL>>>(           // 5
        gxh, gw + 0 * D * D, gw + 1 * D * D, b1a, b1b, ghh, 1);

    // layer 2
    k_gather_h<<<gath_blocks, THREADS>>>(ghh, gxh);               // 6
    k_mlp_hmma<0><<<mlp_blocks, THREADS, SMEM_TOTAL>>>(           // 7
        gxh, gw + 2 * D * D, gw + 3 * D * D, b2a, b2b, d_out, 0);
}